// round 14
// baseline (speedup 1.0000x reference)
#include <cuda_runtime.h>
#include <cuda_bf16.h>
#include <cuda_fp16.h>
#include <math.h>
#include <stdint.h>

#define NN  50000
#define EE  800000
#define GG  128
#define HH  108
#define CH4 27
#define XS  40     // X smem k-stride (bf16)
#define ES  136    // fp32 epilogue row stride

// ---------------- scratch (no allocations allowed) ----------------
__device__ __align__(16) float  g_h0 [NN*HH];
__device__ __align__(16) float  g_h1 [NN*HH];
__device__ __align__(16) __half g_m  [NN*HH];
__device__ __align__(16) float  g_s  [GG*HH];
__device__ __align__(16) float  g_wf [64*HH];
__device__ float g_bf[HH];
__device__ int   g_degi[NN];
__device__ int   g_off [NN];
__device__ int   g_cur [NN];
__device__ int   g_csr [EE];
__device__ float g_cnt[GG];

// ---------------- side streams + events ----------------
struct AuxStreams {
    cudaStream_t s2, s3;
    cudaEvent_t fork, fw, join;
    AuxStreams() {
        cudaStreamCreateWithFlags(&s2, cudaStreamNonBlocking);
        cudaStreamCreateWithFlags(&s3, cudaStreamNonBlocking);
        cudaEventCreateWithFlags(&fork, cudaEventDisableTiming);
        cudaEventCreateWithFlags(&fw,   cudaEventDisableTiming);
        cudaEventCreateWithFlags(&join, cudaEventDisableTiming);
    }
};
static AuxStreams g_aux;

// ---------------- mma.sync m16n8k16 bf16 -> f32 ----------------
__device__ __forceinline__ void mma16816(float* c,
        uint32_t a0, uint32_t a1, uint32_t a2, uint32_t a3,
        uint32_t b0, uint32_t b1) {
    asm volatile(
        "mma.sync.aligned.m16n8k16.row.col.f32.bf16.bf16.f32 "
        "{%0,%1,%2,%3}, {%4,%5,%6,%7}, {%8,%9}, {%0,%1,%2,%3};"
        : "+f"(c[0]), "+f"(c[1]), "+f"(c[2]), "+f"(c[3])
        : "r"(a0), "r"(a1), "r"(a2), "r"(a3), "r"(b0), "r"(b1));
}

__device__ __forceinline__ void split_bf16(float v, __nv_bfloat16& h, __nv_bfloat16& l) {
    h = __float2bfloat16(v);
    l = __float2bfloat16(v - __bfloat162float(h));
}

// stage W[K][108] -> smem transposed/split: Wh/Wl [n(128)][k(WS)] zero-padded
template<int K, int WS, int NT>
__device__ __forceinline__ void stage_W(const float* __restrict__ W,
        __nv_bfloat16* Wh, __nv_bfloat16* Wl, int tid) {
    for (int i = tid; i < 128 * WS; i += NT) {
        int nn = i / WS, k = i - nn * WS;
        float v = (k < K && nn < HH) ? W[k * HH + nn] : 0.f;
        __nv_bfloat16 h, l;
        split_bf16(v, h, l);
        Wh[i] = h; Wl[i] = l;
    }
}

// ---------------- X sources ----------------
struct SrcRow108 {          // [NN][108] fp32 matrix
    const float* X; int row0;
    __device__ __forceinline__ float operator()(int r, int k) const {
        int row = row0 + r;
        return (row < NN && k < HH) ? X[(size_t)row * HH + k] : 0.f;
    }
};
struct SrcHinAggS {         // napply input: [Hin (global), agg (smem fp32)]
    const float* Hin; const float* aggs; int row0;
    __device__ __forceinline__ float operator()(int r, int k) const {
        int row = row0 + r;
        if (row >= NN) return 0.f;
        if (k < HH)  return Hin[(size_t)row * HH + k];
        if (k < 216) return aggs[r * HH + (k - HH)];
        return 0.f;
    }
};

// ---------------- 512-thread mainloop (16 warps, warp tile 32x32) ----------------
template<int KPAD, typename F>
__device__ __forceinline__ void run_mainloop(
        const __nv_bfloat16* __restrict__ Wh, const __nv_bfloat16* __restrict__ Wl,
        const int WS, __nv_bfloat16* Xh, __nv_bfloat16* Xl,
        float (&acc)[2][4][4], int tid, F xsrc) {
    const int l = tid & 31, wid = tid >> 5;
    const int wm = wid & 3, wn = wid >> 2;
    const int NC = KPAD / 32;
    const int BUF = 128 * XS;
    float vreg[8];

    #pragma unroll
    for (int ii = 0; ii < 8; ii++) {
        int i = tid + ii * 512;
        vreg[ii] = xsrc(i >> 5, i & 31);
    }
    #pragma unroll
    for (int ii = 0; ii < 8; ii++) {
        int i = tid + ii * 512;
        int r = i >> 5, kk = i & 31;
        __nv_bfloat16 h, lo;
        split_bf16(vreg[ii], h, lo);
        Xh[r * XS + kk] = h; Xl[r * XS + kk] = lo;
    }
    __syncthreads();

    #pragma unroll
    for (int c = 0; c < NC; c++) {
        if (c + 1 < NC) {
            #pragma unroll
            for (int ii = 0; ii < 8; ii++) {
                int i = tid + ii * 512;
                vreg[ii] = xsrc(i >> 5, (c + 1) * 32 + (i & 31));
            }
        }
        const __nv_bfloat16* xh = Xh + (c & 1) * BUF;
        const __nv_bfloat16* xl = Xl + (c & 1) * BUF;
        const int c0 = c * 32;
        #pragma unroll
        for (int ks = 0; ks < 2; ks++) {
            const int kb = ks * 16;
            uint32_t ah[2][4], al[2][4];
            #pragma unroll
            for (int mt = 0; mt < 2; mt++) {
                int r  = wm * 32 + mt * 16 + (l >> 2);
                int kk = kb + ((l & 3) << 1);
                ah[mt][0] = *(const uint32_t*)&xh[r * XS + kk];
                ah[mt][1] = *(const uint32_t*)&xh[(r + 8) * XS + kk];
                ah[mt][2] = *(const uint32_t*)&xh[r * XS + kk + 8];
                ah[mt][3] = *(const uint32_t*)&xh[(r + 8) * XS + kk + 8];
                al[mt][0] = *(const uint32_t*)&xl[r * XS + kk];
                al[mt][1] = *(const uint32_t*)&xl[(r + 8) * XS + kk];
                al[mt][2] = *(const uint32_t*)&xl[r * XS + kk + 8];
                al[mt][3] = *(const uint32_t*)&xl[(r + 8) * XS + kk + 8];
            }
            #pragma unroll
            for (int nt = 0; nt < 4; nt++) {
                int nn2 = wn * 32 + nt * 8 + (l >> 2);
                int kg  = c0 + kb + ((l & 3) << 1);
                uint32_t bh0 = *(const uint32_t*)&Wh[nn2 * WS + kg];
                uint32_t bh1 = *(const uint32_t*)&Wh[nn2 * WS + kg + 8];
                uint32_t bl0 = *(const uint32_t*)&Wl[nn2 * WS + kg];
                uint32_t bl1 = *(const uint32_t*)&Wl[nn2 * WS + kg + 8];
                #pragma unroll
                for (int mt = 0; mt < 2; mt++) {
                    mma16816(acc[mt][nt], ah[mt][0], ah[mt][1], ah[mt][2], ah[mt][3], bh0, bh1);
                    mma16816(acc[mt][nt], ah[mt][0], ah[mt][1], ah[mt][2], ah[mt][3], bl0, bl1);
                    mma16816(acc[mt][nt], al[mt][0], al[mt][1], al[mt][2], al[mt][3], bh0, bh1);
                }
            }
        }
        if (c + 1 < NC) {
            __nv_bfloat16* dh = Xh + ((c + 1) & 1) * BUF;
            __nv_bfloat16* dl = Xl + ((c + 1) & 1) * BUF;
            #pragma unroll
            for (int ii = 0; ii < 8; ii++) {
                int i = tid + ii * 512;
                int r = i >> 5, kk = i & 31;
                __nv_bfloat16 h, lo;
                split_bf16(vreg[ii], h, lo);
                dh[r * XS + kk] = h; dl[r * XS + kk] = lo;
            }
            __syncthreads();
        }
    }
}

// ---------------- 1024-thread mainloop (32 warps, warp tile 32x16) ----------------
template<int KPAD, typename F>
__device__ __forceinline__ void run_mainloop_w32(
        const __nv_bfloat16* __restrict__ Wh, const __nv_bfloat16* __restrict__ Wl,
        const int WS, __nv_bfloat16* Xh, __nv_bfloat16* Xl,
        float (&acc)[2][2][4], int tid, F xsrc) {
    const int l = tid & 31, wid = tid >> 5;
    const int wm = wid & 3, wn = wid >> 2;     // wn in 0..7
    const int NC = KPAD / 32;
    const int BUF = 128 * XS;
    float vreg[4];

    #pragma unroll
    for (int ii = 0; ii < 4; ii++) {
        int i = tid + ii * 1024;
        vreg[ii] = xsrc(i >> 5, i & 31);
    }
    #pragma unroll
    for (int ii = 0; ii < 4; ii++) {
        int i = tid + ii * 1024;
        int r = i >> 5, kk = i & 31;
        __nv_bfloat16 h, lo;
        split_bf16(vreg[ii], h, lo);
        Xh[r * XS + kk] = h; Xl[r * XS + kk] = lo;
    }
    __syncthreads();

    #pragma unroll
    for (int c = 0; c < NC; c++) {
        if (c + 1 < NC) {
            #pragma unroll
            for (int ii = 0; ii < 4; ii++) {
                int i = tid + ii * 1024;
                vreg[ii] = xsrc(i >> 5, (c + 1) * 32 + (i & 31));
            }
        }
        const __nv_bfloat16* xh = Xh + (c & 1) * BUF;
        const __nv_bfloat16* xl = Xl + (c & 1) * BUF;
        const int c0 = c * 32;
        #pragma unroll
        for (int ks = 0; ks < 2; ks++) {
            const int kb = ks * 16;
            uint32_t ah[2][4], al[2][4];
            #pragma unroll
            for (int mt = 0; mt < 2; mt++) {
                int r  = wm * 32 + mt * 16 + (l >> 2);
                int kk = kb + ((l & 3) << 1);
                ah[mt][0] = *(const uint32_t*)&xh[r * XS + kk];
                ah[mt][1] = *(const uint32_t*)&xh[(r + 8) * XS + kk];
                ah[mt][2] = *(const uint32_t*)&xh[r * XS + kk + 8];
                ah[mt][3] = *(const uint32_t*)&xh[(r + 8) * XS + kk + 8];
                al[mt][0] = *(const uint32_t*)&xl[r * XS + kk];
                al[mt][1] = *(const uint32_t*)&xl[(r + 8) * XS + kk];
                al[mt][2] = *(const uint32_t*)&xl[r * XS + kk + 8];
                al[mt][3] = *(const uint32_t*)&xl[(r + 8) * XS + kk + 8];
            }
            #pragma unroll
            for (int nt = 0; nt < 2; nt++) {
                int nn2 = wn * 16 + nt * 8 + (l >> 2);
                int kg  = c0 + kb + ((l & 3) << 1);
                uint32_t bh0 = *(const uint32_t*)&Wh[nn2 * WS + kg];
                uint32_t bh1 = *(const uint32_t*)&Wh[nn2 * WS + kg + 8];
                uint32_t bl0 = *(const uint32_t*)&Wl[nn2 * WS + kg];
                uint32_t bl1 = *(const uint32_t*)&Wl[nn2 * WS + kg + 8];
                #pragma unroll
                for (int mt = 0; mt < 2; mt++) {
                    mma16816(acc[mt][nt], ah[mt][0], ah[mt][1], ah[mt][2], ah[mt][3], bh0, bh1);
                    mma16816(acc[mt][nt], ah[mt][0], ah[mt][1], ah[mt][2], ah[mt][3], bl0, bl1);
                    mma16816(acc[mt][nt], al[mt][0], al[mt][1], al[mt][2], al[mt][3], bh0, bh1);
                }
            }
        }
        if (c + 1 < NC) {
            __nv_bfloat16* dh = Xh + ((c + 1) & 1) * BUF;
            __nv_bfloat16* dl = Xl + ((c + 1) & 1) * BUF;
            #pragma unroll
            for (int ii = 0; ii < 4; ii++) {
                int i = tid + ii * 1024;
                int r = i >> 5, kk = i & 31;
                __nv_bfloat16 h, lo;
                split_bf16(vreg[ii], h, lo);
                dh[r * XS + kk] = h; dl[r * XS + kk] = lo;
            }
            __syncthreads();
        }
    }
}

__device__ __forceinline__ void zero_acc4(float (&acc)[2][4][4]) {
    #pragma unroll
    for (int mt = 0; mt < 2; mt++)
        #pragma unroll
        for (int nt = 0; nt < 4; nt++)
            #pragma unroll
            for (int i = 0; i < 4; i++) acc[mt][nt][i] = 0.f;
}
__device__ __forceinline__ void zero_acc2(float (&acc)[2][2][4]) {
    #pragma unroll
    for (int mt = 0; mt < 2; mt++)
        #pragma unroll
        for (int nt = 0; nt < 2; nt++)
            #pragma unroll
            for (int i = 0; i < 4; i++) acc[mt][nt][i] = 0.f;
}

// ================= dual GEMM: h0 = X@We+be (fp32); m1 = relu(X@Wf+bf) (fp16) =====
__global__ __launch_bounds__(1024) void gemm_dual(
        const float* __restrict__ X,
        const float* __restrict__ We, const float* __restrict__ be,
        const float* __restrict__ Wf, const float* __restrict__ bf,
        float* __restrict__ h0, __half* __restrict__ m1) {
    const int WSd = 72;
    extern __shared__ char sh[];
    __nv_bfloat16* Weh = (__nv_bfloat16*)sh;
    __nv_bfloat16* Wel = Weh + 128 * WSd;
    __nv_bfloat16* Wfh = Wel + 128 * WSd;
    __nv_bfloat16* Wfl = Wfh + 128 * WSd;
    __nv_bfloat16* Xh  = Wfl + 128 * WSd;     // 2 buffers
    __nv_bfloat16* Xl  = Xh + 2 * 128 * XS;
    float* bse = (float*)(Xl + 2 * 128 * XS);
    float* bsf = bse + 128;

    const int tid = threadIdx.x, l = tid & 31, wid = tid >> 5;
    const int wm = wid & 3, wn = wid >> 2, wnl = wn & 3;
    const int row0 = blockIdx.x * 128;
    const int BUF = 128 * XS;

    for (int i = tid; i < 128 * WSd; i += 1024) {
        int nn = i / WSd, k = i - nn * WSd;
        bool ok = (k < 64 && nn < HH);
        float v1 = ok ? We[k * HH + nn] : 0.f;
        float v2 = ok ? Wf[k * HH + nn] : 0.f;
        __nv_bfloat16 h, lo;
        split_bf16(v1, h, lo); Weh[i] = h; Wel[i] = lo;
        split_bf16(v2, h, lo); Wfh[i] = h; Wfl[i] = lo;
    }
    if (tid < 128) bse[tid] = (tid < HH) ? be[tid] : 0.f;
    else if (tid < 256) { int c2 = tid - 128; bsf[c2] = (c2 < HH) ? bf[c2] : 0.f; }

    const __nv_bfloat16* Whw = (wn < 4) ? Weh : Wfh;
    const __nv_bfloat16* Wlw = (wn < 4) ? Wel : Wfl;

    float acc[2][4][4];
    zero_acc4(acc);

    float vreg[4];
    #pragma unroll
    for (int ii = 0; ii < 4; ii++) {
        int i = tid + ii * 1024;
        int r = i >> 5, kk = i & 31;
        int row = row0 + r;
        vreg[ii] = (row < NN) ? X[(size_t)row * 64 + kk] : 0.f;
    }
    #pragma unroll
    for (int ii = 0; ii < 4; ii++) {
        int i = tid + ii * 1024;
        int r = i >> 5, kk = i & 31;
        __nv_bfloat16 h, lo; split_bf16(vreg[ii], h, lo);
        Xh[r * XS + kk] = h; Xl[r * XS + kk] = lo;
    }
    __syncthreads();

    #pragma unroll
    for (int c = 0; c < 2; c++) {
        if (c == 0) {
            #pragma unroll
            for (int ii = 0; ii < 4; ii++) {
                int i = tid + ii * 1024;
                int r = i >> 5, kk = i & 31;
                int row = row0 + r;
                vreg[ii] = (row < NN) ? X[(size_t)row * 64 + 32 + kk] : 0.f;
            }
        }
        const __nv_bfloat16* xh = Xh + (c & 1) * BUF;
        const __nv_bfloat16* xl = Xl + (c & 1) * BUF;
        const int c0 = c * 32;
        #pragma unroll
        for (int ks = 0; ks < 2; ks++) {
            const int kb = ks * 16;
            #pragma unroll
            for (int mt = 0; mt < 2; mt++) {
                int r  = wm * 32 + mt * 16 + (l >> 2);
                int kk = kb + ((l & 3) << 1);
                uint32_t a0 = *(const uint32_t*)&xh[r * XS + kk];
                uint32_t a1 = *(const uint32_t*)&xh[(r + 8) * XS + kk];
                uint32_t a2 = *(const uint32_t*)&xh[r * XS + kk + 8];
                uint32_t a3 = *(const uint32_t*)&xh[(r + 8) * XS + kk + 8];
                uint32_t b0 = *(const uint32_t*)&xl[r * XS + kk];
                uint32_t b1 = *(const uint32_t*)&xl[(r + 8) * XS + kk];
                uint32_t b2 = *(const uint32_t*)&xl[r * XS + kk + 8];
                uint32_t b3 = *(const uint32_t*)&xl[(r + 8) * XS + kk + 8];
                #pragma unroll
                for (int nt = 0; nt < 4; nt++) {
                    int nn2 = wnl * 32 + nt * 8 + (l >> 2);
                    int kg  = c0 + kb + ((l & 3) << 1);
                    uint32_t bh0 = *(const uint32_t*)&Whw[nn2 * WSd + kg];
                    uint32_t bh1 = *(const uint32_t*)&Whw[nn2 * WSd + kg + 8];
                    uint32_t bl0 = *(const uint32_t*)&Wlw[nn2 * WSd + kg];
                    uint32_t bl1 = *(const uint32_t*)&Wlw[nn2 * WSd + kg + 8];
                    mma16816(acc[mt][nt], a0, a1, a2, a3, bh0, bh1);
                    mma16816(acc[mt][nt], a0, a1, a2, a3, bl0, bl1);
                    mma16816(acc[mt][nt], b0, b1, b2, b3, bh0, bh1);
                }
            }
        }
        if (c == 0) {
            __nv_bfloat16* dh = Xh + BUF;
            __nv_bfloat16* dl = Xl + BUF;
            #pragma unroll
            for (int ii = 0; ii < 4; ii++) {
                int i = tid + ii * 1024;
                int r = i >> 5, kk = i & 31;
                __nv_bfloat16 h, lo; split_bf16(vreg[ii], h, lo);
                dh[r * XS + kk] = h; dl[r * XS + kk] = lo;
            }
            __syncthreads();
        }
    }

    #pragma unroll
    for (int mt = 0; mt < 2; mt++) {
        #pragma unroll
        for (int nt = 0; nt < 4; nt++) {
            int colL = wnl * 32 + nt * 8 + ((l & 3) << 1);
            if (colL < HH) {
                int r   = wm * 32 + mt * 16 + (l >> 2);
                int row = row0 + r;
                if (wn < 4) {
                    float v0 = acc[mt][nt][0] + bse[colL];
                    float v1 = acc[mt][nt][1] + bse[colL + 1];
                    float v2 = acc[mt][nt][2] + bse[colL];
                    float v3 = acc[mt][nt][3] + bse[colL + 1];
                    if (row < NN)     *(float2*)&h0[(size_t)row * HH + colL]       = make_float2(v0, v1);
                    if (row + 8 < NN) *(float2*)&h0[(size_t)(row + 8) * HH + colL] = make_float2(v2, v3);
                } else {
                    float v0 = fmaxf(acc[mt][nt][0] + bsf[colL], 0.f);
                    float v1 = fmaxf(acc[mt][nt][1] + bsf[colL + 1], 0.f);
                    float v2 = fmaxf(acc[mt][nt][2] + bsf[colL], 0.f);
                    float v3 = fmaxf(acc[mt][nt][3] + bsf[colL + 1], 0.f);
                    if (row < NN)     *(__half2*)&m1[(size_t)row * HH + colL]       = __floats2half2_rn(v0, v1);
                    if (row + 8 < NN) *(__half2*)&m1[(size_t)(row + 8) * HH + colL] = __floats2half2_rn(v2, v3);
                }
            }
        }
    }
}

// ================= pool2 GEMM (512 thr, 2 blocks/SM) =================
__global__ __launch_bounds__(512, 2) void gemm_pool2(
        const float* __restrict__ X, const float* __restrict__ W,
        const float* __restrict__ b, __half* __restrict__ Y) {
    const int WS = 136;
    extern __shared__ char sh[];
    __nv_bfloat16* Wh = (__nv_bfloat16*)sh;
    __nv_bfloat16* Wl = Wh + 128 * WS;
    __nv_bfloat16* Xh = Wl + 128 * WS;
    __nv_bfloat16* Xl = Xh + 2 * 128 * XS;
    float* bs = (float*)(Xl + 2 * 128 * XS);

    const int tid = threadIdx.x, l = tid & 31, wid = tid >> 5;
    const int wm = wid & 3, wn = wid >> 2;
    const int row0 = blockIdx.x * 128;

    stage_W<108, WS, 512>(W, Wh, Wl, tid);
    if (tid < 128) bs[tid] = (tid < HH) ? b[tid] : 0.f;

    float acc[2][4][4];
    zero_acc4(acc);
    run_mainloop<128>(Wh, Wl, WS, Xh, Xl, acc, tid, SrcRow108{X, row0});

    #pragma unroll
    for (int mt = 0; mt < 2; mt++) {
        #pragma unroll
        for (int nt = 0; nt < 4; nt++) {
            int col = wn * 32 + nt * 8 + ((l & 3) << 1);
            if (col < HH) {
                int r   = wm * 32 + mt * 16 + (l >> 2);
                int row = row0 + r;
                float v0 = fmaxf(acc[mt][nt][0] + bs[col], 0.f);
                float v1 = fmaxf(acc[mt][nt][1] + bs[col + 1], 0.f);
                float v2 = fmaxf(acc[mt][nt][2] + bs[col], 0.f);
                float v3 = fmaxf(acc[mt][nt][3] + bs[col + 1], 0.f);
                if (row < NN)     *(__half2*)&Y[(size_t)row * HH + col]       = __floats2half2_rn(v0, v1);
                if (row + 8 < NN) *(__half2*)&Y[(size_t)(row + 8) * HH + col] = __floats2half2_rn(v2, v3);
            }
        }
    }
}

// ================= fused gather + node apply (1024 threads, 32 warps) =============
// Prologue: block-local CSR gather of this block's 128 rows -> smem agg (fp32 mean).
// Mainloop: [Hin, agg] @ Wn. Epilogue: norm+residual+relu (+ optional graph pool).
template<bool POOL>
__global__ __launch_bounds__(1024) void mma_napply(
        const float* __restrict__ Hin, const __half* __restrict__ m,
        const int* __restrict__ off, const int* __restrict__ csr,
        const float* __restrict__ W, const float* __restrict__ b,
        float* __restrict__ Hout, const int* __restrict__ gid,
        float* __restrict__ s) {
    const int WS = 232;
    extern __shared__ char sh[];
    __nv_bfloat16* Wh = (__nv_bfloat16*)sh;
    __nv_bfloat16* Wl = Wh + 128 * WS;
    __nv_bfloat16* Xh = Wl + 128 * WS;
    __nv_bfloat16* Xl = Xh + 2 * 128 * XS;
    float* bs   = (float*)(Xl + 2 * 128 * XS);   // 128 floats
    int*   gds  = (int*)(bs + 128);              // 128 ints
    float* aggs = (float*)(gds + 128);           // 128*108 fp32 = 55,296 B
    float* epi  = (float*)sh;                    // aliases W region after mainloop

    const int tid = threadIdx.x, l = tid & 31, wid = tid >> 5;
    const int wm = wid & 3, wn = wid >> 2;   // wn in 0..7
    const int row0 = blockIdx.x * 128;

    stage_W<216, WS, 1024>(W, Wh, Wl, tid);
    if (tid < 128) {
        bs[tid] = (tid < HH) ? b[tid] : 0.f;
        if (POOL) gds[tid] = (row0 + tid < NN) ? gid[row0 + tid] : -1;
    }

    // ---- block-local gather: warp wid handles rows wid*4 .. wid*4+3 ----
    #pragma unroll
    for (int rr = 0; rr < 4; rr++) {
        int r = wid * 4 + rr;
        int row = row0 + r;
        if (row >= NN) continue;
        int s0 = off[row];
        int s1 = (row + 1 < NN) ? off[row + 1] : EE;
        if (l < CH4) {
            float4 a0 = make_float4(0.f,0.f,0.f,0.f), a1 = a0, a2 = a0, a3 = a0;
            int j = s0;
            for (; j + 3 < s1; j += 4) {
                int i0 = csr[j], i1 = csr[j+1], i2 = csr[j+2], i3 = csr[j+3];
                uint2 q0 = *(const uint2*)(m + (size_t)i0 * HH + l * 4);
                uint2 q1 = *(const uint2*)(m + (size_t)i1 * HH + l * 4);
                uint2 q2 = *(const uint2*)(m + (size_t)i2 * HH + l * 4);
                uint2 q3 = *(const uint2*)(m + (size_t)i3 * HH + l * 4);
                float2 f;
                f = __half22float2(*(__half2*)&q0.x); a0.x += f.x; a0.y += f.y;
                f = __half22float2(*(__half2*)&q0.y); a0.z += f.x; a0.w += f.y;
                f = __half22float2(*(__half2*)&q1.x); a1.x += f.x; a1.y += f.y;
                f = __half22float2(*(__half2*)&q1.y); a1.z += f.x; a1.w += f.y;
                f = __half22float2(*(__half2*)&q2.x); a2.x += f.x; a2.y += f.y;
                f = __half22float2(*(__half2*)&q2.y); a2.z += f.x; a2.w += f.y;
                f = __half22float2(*(__half2*)&q3.x); a3.x += f.x; a3.y += f.y;
                f = __half22float2(*(__half2*)&q3.y); a3.z += f.x; a3.w += f.y;
            }
            for (; j < s1; j++) {
                int i0 = csr[j];
                uint2 q0 = *(const uint2*)(m + (size_t)i0 * HH + l * 4);
                float2 f0 = __half22float2(*(__half2*)&q0.x);
                float2 f1 = __half22float2(*(__half2*)&q0.y);
                a0.x += f0.x; a0.y += f0.y; a0.z += f1.x; a0.w += f1.y;
            }
            float inv = 1.f / fmaxf((float)(s1 - s0), 1.f);
            a0.x = (a0.x + a1.x + a2.x + a3.x) * inv;
            a0.y = (a0.y + a1.y + a2.y + a3.y) * inv;
            a0.z = (a0.z + a1.z + a2.z + a3.z) * inv;
            a0.w = (a0.w + a1.w + a2.w + a3.w) * inv;
            *(float4*)&aggs[r * HH + l * 4] = a0;
        }
    }
    __syncthreads();   // aggs ready for mainloop staging

    float acc[2][2][4];
    zero_acc2(acc);
    run_mainloop_w32<224>(Wh, Wl, WS, Xh, Xl, acc, tid, SrcHinAggS{Hin, aggs, row0});

    __syncthreads();   // W reads done -> alias epi
    #pragma unroll
    for (int mt = 0; mt < 2; mt++) {
        #pragma unroll
        for (int nt = 0; nt < 2; nt++) {
            int col = wn * 16 + nt * 8 + ((l & 3) << 1);
            int r   = wm * 32 + mt * 16 + (l >> 2);
            *(float2*)&epi[r * ES + col] =
                make_float2(acc[mt][nt][0] + bs[col], acc[mt][nt][1] + bs[col + 1]);
            *(float2*)&epi[(r + 8) * ES + col] =
                make_float2(acc[mt][nt][2] + bs[col], acc[mt][nt][3] + bs[col + 1]);
        }
    }
    __syncthreads();

    // norm + residual + relu: 32 warps x 4 rows
    #pragma unroll
    for (int rr = 0; rr < 4; rr++) {
        int r = wid * 4 + rr;
        int row = row0 + r;
        if (row >= NN) continue;
        float v[4]; float sn = 0.f;
        #pragma unroll
        for (int j = 0; j < 4; j++) {
            int c = l + 32 * j;
            v[j] = (c < HH) ? epi[r * ES + c] : 0.f;
            sn += v[j] * v[j];
        }
        #pragma unroll
        for (int off2 = 16; off2 > 0; off2 >>= 1)
            sn += __shfl_xor_sync(0xffffffffu, sn, off2);
        float inv = 1.f / fmaxf(sqrtf(sn), 1e-12f);
        #pragma unroll
        for (int j = 0; j < 4; j++) {
            int c = l + 32 * j;
            if (c < HH) {
                float o = Hin[(size_t)row * HH + c] + fmaxf(v[j] * inv, 0.f);
                if (POOL) epi[r * ES + c] = o;
                else      Hout[(size_t)row * HH + c] = o;
            }
        }
    }

    if (POOL) {
        __syncthreads();
        // per-graph column sums: 8 segments x 128 cols; gid sorted -> few runs
        int col = tid & 127, seg = tid >> 7;
        if (col < HH) {
            float a = 0.f; int curg = -1;
            #pragma unroll 4
            for (int r = seg * 16; r < seg * 16 + 16; r++) {
                int g = gds[r];
                if (g < 0) break;
                if (g != curg) {
                    if (curg >= 0) atomicAdd(&s[curg * HH + col], a);
                    curg = g; a = 0.f;
                }
                a += epi[r * ES + col];
            }
            if (curg >= 0) atomicAdd(&s[curg * HH + col], a);
        }
    }
}

// ================= weight fusion: Wf = We@Wp1, bf = be@Wp1 + bp1 =================
__global__ __launch_bounds__(256) void fuse_w(
        const float* __restrict__ We, const float* __restrict__ be,
        const float* __restrict__ Wp, const float* __restrict__ bp,
        float* __restrict__ Wf, float* __restrict__ bf) {
    __shared__ float sWp[HH * HH];
    for (int i = threadIdx.x; i < HH * HH; i += 256) sWp[i] = Wp[i];
    __syncthreads();
    int t = blockIdx.x * 256 + threadIdx.x;
    if (t < 64 * HH) {
        int i = t / HH, j = t - (t / HH) * HH;
        const float* we = We + i * HH;
        float s0 = 0.f, s1 = 0.f;
        #pragma unroll 4
        for (int k = 0; k < HH; k += 2) {
            s0 = fmaf(we[k],     sWp[k * HH + j],       s0);
            s1 = fmaf(we[k + 1], sWp[(k + 1) * HH + j], s1);
        }
        Wf[t] = s0 + s1;
    } else if (t < 64 * HH + HH) {
        int j = t - 64 * HH;
        float s0 = bp[j], s1 = 0.f;
        #pragma unroll 4
        for (int k = 0; k < HH; k += 2) {
            s0 = fmaf(be[k],     sWp[k * HH + j],       s0);
            s1 = fmaf(be[k + 1], sWp[(k + 1) * HH + j], s1);
        }
        bf[j] = s0 + s1;
    }
}

// ================= graph prep =================
__global__ void deg_cnt_kernel(const int* __restrict__ dst, const int* __restrict__ gid,
                               int* __restrict__ degi, float* __restrict__ cnt) {
    int tk = blockIdx.x * blockDim.x + threadIdx.x;
    if (tk < EE) atomicAdd(&degi[dst[tk]], 1);
    if (tk < NN) atomicAdd(&cnt[gid[tk]], 1.f);
}

__global__ void scan_block(const int* __restrict__ degi, int* __restrict__ off,
                           int* __restrict__ cur) {
    __shared__ int wt[32];
    const int PER = 49;
    int t = threadIdx.x, lane = t & 31, w = t >> 5;
    int base = t * PER;
    int sum = 0;
    for (int j = 0; j < PER; j++) {
        int idx = base + j;
        if (idx < NN) sum += degi[idx];
    }
    int v = sum;
    #pragma unroll
    for (int d = 1; d < 32; d <<= 1) {
        int u = __shfl_up_sync(0xffffffffu, v, d);
        if (lane >= d) v += u;
    }
    if (lane == 31) wt[w] = v;
    __syncthreads();
    if (w == 0) {
        int x = wt[lane];
        #pragma unroll
        for (int d = 1; d < 32; d <<= 1) {
            int u = __shfl_up_sync(0xffffffffu, x, d);
            if (lane >= d) x += u;
        }
        wt[lane] = x;
    }
    __syncthreads();
    int run = v - sum + (w > 0 ? wt[w - 1] : 0);
    for (int j = 0; j < PER; j++) {
        int idx = base + j;
        if (idx < NN) {
            int d0 = degi[idx];
            off[idx] = run;
            cur[idx] = run;
            run += d0;
        }
    }
}

__global__ void csr_fill(const int* __restrict__ src, const int* __restrict__ dst,
                         int* __restrict__ cur, int* __restrict__ csr) {
    int e = blockIdx.x * blockDim.x + threadIdx.x;
    if (e < EE) {
        int d = dst[e];
        int pidx = atomicAdd(&cur[d], 1);
        csr[pidx] = src[e];
    }
}

// ================= readout finalize =================
__global__ void finalize(const float* __restrict__ s, const float* __restrict__ cnt,
                         float* __restrict__ out) {
    int tk = blockIdx.x * blockDim.x + threadIdx.x;
    if (tk < GG * HH) {
        int g = tk / HH;
        out[tk] = s[tk] / fmaxf(cnt[g], 1.f);
    }
}

// ================= launch =================
extern "C" void kernel_launch(void* const* d_in, const int* in_sizes, int n_in,
                              void* d_out, int out_size) {
    const float* nodes_feat = (const float*)d_in[0];
    const int*   src  = (const int*)d_in[4];
    const int*   dst  = (const int*)d_in[5];
    const int*   gid  = (const int*)d_in[6];
    const float* W_emb = (const float*)d_in[7];
    const float* b_emb = (const float*)d_in[8];
    const float* Wp1   = (const float*)d_in[9];
    const float* bp1   = (const float*)d_in[10];
    const float* Wn1   = (const float*)d_in[11];
    const float* bn1   = (const float*)d_in[12];
    const float* Wp2   = (const float*)d_in[13];
    const float* bp2   = (const float*)d_in[14];
    const float* Wn2   = (const float*)d_in[15];
    const float* bn2   = (const float*)d_in[16];
    float* out = (float*)d_out;

    float *p_h0, *p_h1, *p_s, *p_cnt, *p_wf, *p_bf;
    __half *p_m;
    int *p_degi, *p_off, *p_cur, *p_csr;
    cudaGetSymbolAddress((void**)&p_h0,   g_h0);
    cudaGetSymbolAddress((void**)&p_h1,   g_h1);
    cudaGetSymbolAddress((void**)&p_m,    g_m);
    cudaGetSymbolAddress((void**)&p_s,    g_s);
    cudaGetSymbolAddress((void**)&p_cnt,  g_cnt);
    cudaGetSymbolAddress((void**)&p_wf,   g_wf);
    cudaGetSymbolAddress((void**)&p_bf,   g_bf);
    cudaGetSymbolAddress((void**)&p_degi, g_degi);
    cudaGetSymbolAddress((void**)&p_off,  g_off);
    cudaGetSymbolAddress((void**)&p_cur,  g_cur);
    cudaGetSymbolAddress((void**)&p_csr,  g_csr);

    const int smem_dual = 4*(128*72*2) + 2*(2*128*XS*2) + 1024;            // 115,712
    const int smem_pool = 2*(128*136*2) + 2*(2*128*XS*2) + 512;            // 111,104
    const int smem_na   = 2*(128*232*2) + 2*(2*128*XS*2) + 1024 + 128*HH*4; // 216,064
    cudaFuncSetAttribute(gemm_dual,         cudaFuncAttributeMaxDynamicSharedMemorySize, smem_dual);
    cudaFuncSetAttribute(gemm_pool2,        cudaFuncAttributeMaxDynamicSharedMemorySize, smem_pool);
    cudaFuncSetAttribute(mma_napply<false>, cudaFuncAttributeMaxDynamicSharedMemorySize, smem_na);
    cudaFuncSetAttribute(mma_napply<true>,  cudaFuncAttributeMaxDynamicSharedMemorySize, smem_na);

    const int mma_blocks = (NN + 127) / 128;        // 391

    // fork FIRST: fuse_w (s3) and CSR chain (s2) start immediately
    cudaEventRecord(g_aux.fork, 0);
    cudaStreamWaitEvent(g_aux.s3, g_aux.fork, 0);
    cudaStreamWaitEvent(g_aux.s2, g_aux.fork, 0);

    // s3: weight folding (dual dep)
    fuse_w<<<28, 256, 0, g_aux.s3>>>(W_emb, b_emb, Wp1, bp1, p_wf, p_bf);
    cudaEventRecord(g_aux.fw, g_aux.s3);

    // s2: degree/count zero-init + CSR chain (self-contained)
    cudaMemsetAsync(p_degi, 0, (size_t)NN * sizeof(int), g_aux.s2);
    cudaMemsetAsync(p_cnt,  0, (size_t)GG * sizeof(float), g_aux.s2);
    deg_cnt_kernel<<<(EE + 255) / 256, 256, 0, g_aux.s2>>>(dst, gid, p_degi, p_cnt);
    scan_block<<<1, 1024, 0, g_aux.s2>>>(p_degi, p_off, p_cur);
    csr_fill<<<(EE + 255) / 256, 256, 0, g_aux.s2>>>(src, dst, p_cur, p_csr);
    cudaEventRecord(g_aux.join, g_aux.s2);

    // default: readout zero-init, then dual (waits fuse_w)
    cudaMemsetAsync(p_s, 0, (size_t)GG * HH * sizeof(float));
    cudaStreamWaitEvent(0, g_aux.fw, 0);
    gemm_dual<<<mma_blocks, 1024, smem_dual>>>(nodes_feat, W_emb, b_emb, p_wf, p_bf, p_h0, p_m);

    cudaStreamWaitEvent(0, g_aux.join, 0);   // napply gather needs CSR + m

    mma_napply<false><<<mma_blocks, 1024, smem_na>>>(p_h0, p_m, p_off, p_csr,
                                                     Wn1, bn1, p_h1, nullptr, nullptr);
    gemm_pool2<<<mma_blocks, 512, smem_pool>>>(p_h1, Wp2, bp2, p_m);
    mma_napply<true><<<mma_blocks, 1024, smem_na>>>(p_h1, p_m, p_off, p_csr,
                                                    Wn2, bn2, nullptr, gid, p_s);
    finalize<<<(GG * HH + 127) / 128, 128>>>(p_s, p_cnt, out);
}

// round 15
// speedup vs baseline: 1.2687x; 1.2687x over previous
#include <cuda_runtime.h>
#include <cuda_bf16.h>
#include <cuda_fp16.h>
#include <math.h>
#include <stdint.h>

#define NN  50000
#define EE  800000
#define GG  128
#define HH  108
#define CH4 27
#define XS  40     // X smem k-stride (bf16)
#define ES  136    // fp32 epilogue row stride
#define NB  391    // row blocks of 128
#define NBA 196    // half A blocks (rows [0, 25088))
#define NSPLIT (NBA*128)

// ---------------- scratch (no allocations allowed) ----------------
__device__ __align__(16) float  g_h0 [NN*HH];
__device__ __align__(16) float  g_h1 [NN*HH];
__device__ __align__(16) __half g_m  [NN*HH];
__device__ __align__(16) __half g_aggh[NN*HH];
__device__ __align__(16) float  g_s  [GG*HH];
__device__ __align__(16) float  g_wf [64*HH];
__device__ float g_bf[HH];
__device__ int   g_degi[NN];
__device__ int   g_off [NN];
__device__ int   g_cur [NN];
__device__ int   g_csr [EE];
__device__ float g_cnt[GG];

// ---------------- side streams + events ----------------
struct AuxStreams {
    cudaStream_t s2, s3;
    cudaEvent_t fork, fw, csrdone, duald, evB;
    AuxStreams() {
        cudaStreamCreateWithFlags(&s2, cudaStreamNonBlocking);
        cudaStreamCreateWithFlags(&s3, cudaStreamNonBlocking);
        cudaEventCreateWithFlags(&fork,    cudaEventDisableTiming);
        cudaEventCreateWithFlags(&fw,      cudaEventDisableTiming);
        cudaEventCreateWithFlags(&csrdone, cudaEventDisableTiming);
        cudaEventCreateWithFlags(&duald,   cudaEventDisableTiming);
        cudaEventCreateWithFlags(&evB,     cudaEventDisableTiming);
    }
};
static AuxStreams g_aux;

// ---------------- mma.sync m16n8k16 bf16 -> f32 ----------------
__device__ __forceinline__ void mma16816(float* c,
        uint32_t a0, uint32_t a1, uint32_t a2, uint32_t a3,
        uint32_t b0, uint32_t b1) {
    asm volatile(
        "mma.sync.aligned.m16n8k16.row.col.f32.bf16.bf16.f32 "
        "{%0,%1,%2,%3}, {%4,%5,%6,%7}, {%8,%9}, {%0,%1,%2,%3};"
        : "+f"(c[0]), "+f"(c[1]), "+f"(c[2]), "+f"(c[3])
        : "r"(a0), "r"(a1), "r"(a2), "r"(a3), "r"(b0), "r"(b1));
}

__device__ __forceinline__ void split_bf16(float v, __nv_bfloat16& h, __nv_bfloat16& l) {
    h = __float2bfloat16(v);
    l = __float2bfloat16(v - __bfloat162float(h));
}

// stage W[K][108] -> smem transposed/split: Wh/Wl [n(128)][k(WS)] zero-padded
template<int K, int WS, int NT>
__device__ __forceinline__ void stage_W(const float* __restrict__ W,
        __nv_bfloat16* Wh, __nv_bfloat16* Wl, int tid) {
    for (int i = tid; i < 128 * WS; i += NT) {
        int nn = i / WS, k = i - nn * WS;
        float v = (k < K && nn < HH) ? W[k * HH + nn] : 0.f;
        __nv_bfloat16 h, l;
        split_bf16(v, h, l);
        Wh[i] = h; Wl[i] = l;
    }
}

// ---------------- X sources ----------------
struct SrcRow108 {
    const float* X; int row0;
    __device__ __forceinline__ float operator()(int r, int k) const {
        int row = row0 + r;
        return (row < NN && k < HH) ? X[(size_t)row * HH + k] : 0.f;
    }
};
struct SrcHinAgg {
    const float* Hin; const __half* aggh; int row0;
    __device__ __forceinline__ float operator()(int r, int k) const {
        int row = row0 + r;
        if (row >= NN) return 0.f;
        if (k < HH)  return Hin[(size_t)row * HH + k];
        if (k < 216) return __half2float(aggh[(size_t)row * HH + (k - HH)]);
        return 0.f;
    }
};

// ---------------- 512-thread mainloop (16 warps, warp tile 32x32) ----------------
template<int KPAD, typename F>
__device__ __forceinline__ void run_mainloop(
        const __nv_bfloat16* __restrict__ Wh, const __nv_bfloat16* __restrict__ Wl,
        const int WS, __nv_bfloat16* Xh, __nv_bfloat16* Xl,
        float (&acc)[2][4][4], int tid, F xsrc) {
    const int l = tid & 31, wid = tid >> 5;
    const int wm = wid & 3, wn = wid >> 2;
    const int NC = KPAD / 32;
    const int BUF = 128 * XS;
    float vreg[8];

    #pragma unroll
    for (int ii = 0; ii < 8; ii++) {
        int i = tid + ii * 512;
        vreg[ii] = xsrc(i >> 5, i & 31);
    }
    #pragma unroll
    for (int ii = 0; ii < 8; ii++) {
        int i = tid + ii * 512;
        int r = i >> 5, kk = i & 31;
        __nv_bfloat16 h, lo;
        split_bf16(vreg[ii], h, lo);
        Xh[r * XS + kk] = h; Xl[r * XS + kk] = lo;
    }
    __syncthreads();

    #pragma unroll
    for (int c = 0; c < NC; c++) {
        if (c + 1 < NC) {
            #pragma unroll
            for (int ii = 0; ii < 8; ii++) {
                int i = tid + ii * 512;
                vreg[ii] = xsrc(i >> 5, (c + 1) * 32 + (i & 31));
            }
        }
        const __nv_bfloat16* xh = Xh + (c & 1) * BUF;
        const __nv_bfloat16* xl = Xl + (c & 1) * BUF;
        const int c0 = c * 32;
        #pragma unroll
        for (int ks = 0; ks < 2; ks++) {
            const int kb = ks * 16;
            uint32_t ah[2][4], al[2][4];
            #pragma unroll
            for (int mt = 0; mt < 2; mt++) {
                int r  = wm * 32 + mt * 16 + (l >> 2);
                int kk = kb + ((l & 3) << 1);
                ah[mt][0] = *(const uint32_t*)&xh[r * XS + kk];
                ah[mt][1] = *(const uint32_t*)&xh[(r + 8) * XS + kk];
                ah[mt][2] = *(const uint32_t*)&xh[r * XS + kk + 8];
                ah[mt][3] = *(const uint32_t*)&xh[(r + 8) * XS + kk + 8];
                al[mt][0] = *(const uint32_t*)&xl[r * XS + kk];
                al[mt][1] = *(const uint32_t*)&xl[(r + 8) * XS + kk];
                al[mt][2] = *(const uint32_t*)&xl[r * XS + kk + 8];
                al[mt][3] = *(const uint32_t*)&xl[(r + 8) * XS + kk + 8];
            }
            #pragma unroll
            for (int nt = 0; nt < 4; nt++) {
                int nn2 = wn * 32 + nt * 8 + (l >> 2);
                int kg  = c0 + kb + ((l & 3) << 1);
                uint32_t bh0 = *(const uint32_t*)&Wh[nn2 * WS + kg];
                uint32_t bh1 = *(const uint32_t*)&Wh[nn2 * WS + kg + 8];
                uint32_t bl0 = *(const uint32_t*)&Wl[nn2 * WS + kg];
                uint32_t bl1 = *(const uint32_t*)&Wl[nn2 * WS + kg + 8];
                #pragma unroll
                for (int mt = 0; mt < 2; mt++) {
                    mma16816(acc[mt][nt], ah[mt][0], ah[mt][1], ah[mt][2], ah[mt][3], bh0, bh1);
                    mma16816(acc[mt][nt], ah[mt][0], ah[mt][1], ah[mt][2], ah[mt][3], bl0, bl1);
                    mma16816(acc[mt][nt], al[mt][0], al[mt][1], al[mt][2], al[mt][3], bh0, bh1);
                }
            }
        }
        if (c + 1 < NC) {
            __nv_bfloat16* dh = Xh + ((c + 1) & 1) * BUF;
            __nv_bfloat16* dl = Xl + ((c + 1) & 1) * BUF;
            #pragma unroll
            for (int ii = 0; ii < 8; ii++) {
                int i = tid + ii * 512;
                int r = i >> 5, kk = i & 31;
                __nv_bfloat16 h, lo;
                split_bf16(vreg[ii], h, lo);
                dh[r * XS + kk] = h; dl[r * XS + kk] = lo;
            }
            __syncthreads();
        }
    }
}

// ---------------- 1024-thread mainloop (32 warps, warp tile 32x16) ----------------
template<int KPAD, typename F>
__device__ __forceinline__ void run_mainloop_w32(
        const __nv_bfloat16* __restrict__ Wh, const __nv_bfloat16* __restrict__ Wl,
        const int WS, __nv_bfloat16* Xh, __nv_bfloat16* Xl,
        float (&acc)[2][2][4], int tid, F xsrc) {
    const int l = tid & 31, wid = tid >> 5;
    const int wm = wid & 3, wn = wid >> 2;
    const int NC = KPAD / 32;
    const int BUF = 128 * XS;
    float vreg[4];

    #pragma unroll
    for (int ii = 0; ii < 4; ii++) {
        int i = tid + ii * 1024;
        vreg[ii] = xsrc(i >> 5, i & 31);
    }
    #pragma unroll
    for (int ii = 0; ii < 4; ii++) {
        int i = tid + ii * 1024;
        int r = i >> 5, kk = i & 31;
        __nv_bfloat16 h, lo;
        split_bf16(vreg[ii], h, lo);
        Xh[r * XS + kk] = h; Xl[r * XS + kk] = lo;
    }
    __syncthreads();

    #pragma unroll
    for (int c = 0; c < NC; c++) {
        if (c + 1 < NC) {
            #pragma unroll
            for (int ii = 0; ii < 4; ii++) {
                int i = tid + ii * 1024;
                vreg[ii] = xsrc(i >> 5, (c + 1) * 32 + (i & 31));
            }
        }
        const __nv_bfloat16* xh = Xh + (c & 1) * BUF;
        const __nv_bfloat16* xl = Xl + (c & 1) * BUF;
        const int c0 = c * 32;
        #pragma unroll
        for (int ks = 0; ks < 2; ks++) {
            const int kb = ks * 16;
            uint32_t ah[2][4], al[2][4];
            #pragma unroll
            for (int mt = 0; mt < 2; mt++) {
                int r  = wm * 32 + mt * 16 + (l >> 2);
                int kk = kb + ((l & 3) << 1);
                ah[mt][0] = *(const uint32_t*)&xh[r * XS + kk];
                ah[mt][1] = *(const uint32_t*)&xh[(r + 8) * XS + kk];
                ah[mt][2] = *(const uint32_t*)&xh[r * XS + kk + 8];
                ah[mt][3] = *(const uint32_t*)&xh[(r + 8) * XS + kk + 8];
                al[mt][0] = *(const uint32_t*)&xl[r * XS + kk];
                al[mt][1] = *(const uint32_t*)&xl[(r + 8) * XS + kk];
                al[mt][2] = *(const uint32_t*)&xl[r * XS + kk + 8];
                al[mt][3] = *(const uint32_t*)&xl[(r + 8) * XS + kk + 8];
            }
            #pragma unroll
            for (int nt = 0; nt < 2; nt++) {
                int nn2 = wn * 16 + nt * 8 + (l >> 2);
                int kg  = c0 + kb + ((l & 3) << 1);
                uint32_t bh0 = *(const uint32_t*)&Wh[nn2 * WS + kg];
                uint32_t bh1 = *(const uint32_t*)&Wh[nn2 * WS + kg + 8];
                uint32_t bl0 = *(const uint32_t*)&Wl[nn2 * WS + kg];
                uint32_t bl1 = *(const uint32_t*)&Wl[nn2 * WS + kg + 8];
                #pragma unroll
                for (int mt = 0; mt < 2; mt++) {
                    mma16816(acc[mt][nt], ah[mt][0], ah[mt][1], ah[mt][2], ah[mt][3], bh0, bh1);
                    mma16816(acc[mt][nt], ah[mt][0], ah[mt][1], ah[mt][2], ah[mt][3], bl0, bl1);
                    mma16816(acc[mt][nt], al[mt][0], al[mt][1], al[mt][2], al[mt][3], bh0, bh1);
                }
            }
        }
        if (c + 1 < NC) {
            __nv_bfloat16* dh = Xh + ((c + 1) & 1) * BUF;
            __nv_bfloat16* dl = Xl + ((c + 1) & 1) * BUF;
            #pragma unroll
            for (int ii = 0; ii < 4; ii++) {
                int i = tid + ii * 1024;
                int r = i >> 5, kk = i & 31;
                __nv_bfloat16 h, lo;
                split_bf16(vreg[ii], h, lo);
                dh[r * XS + kk] = h; dl[r * XS + kk] = lo;
            }
            __syncthreads();
        }
    }
}

__device__ __forceinline__ void zero_acc4(float (&acc)[2][4][4]) {
    #pragma unroll
    for (int mt = 0; mt < 2; mt++)
        #pragma unroll
        for (int nt = 0; nt < 4; nt++)
            #pragma unroll
            for (int i = 0; i < 4; i++) acc[mt][nt][i] = 0.f;
}
__device__ __forceinline__ void zero_acc2(float (&acc)[2][2][4]) {
    #pragma unroll
    for (int mt = 0; mt < 2; mt++)
        #pragma unroll
        for (int nt = 0; nt < 2; nt++)
            #pragma unroll
            for (int i = 0; i < 4; i++) acc[mt][nt][i] = 0.f;
}

// ================= dual GEMM: h0 = X@We+be (fp32); m1 = relu(X@Wf+bf) (fp16) =====
__global__ __launch_bounds__(1024) void gemm_dual(
        const float* __restrict__ X,
        const float* __restrict__ We, const float* __restrict__ be,
        const float* __restrict__ Wf, const float* __restrict__ bf,
        float* __restrict__ h0, __half* __restrict__ m1) {
    const int WSd = 72;
    extern __shared__ char sh[];
    __nv_bfloat16* Weh = (__nv_bfloat16*)sh;
    __nv_bfloat16* Wel = Weh + 128 * WSd;
    __nv_bfloat16* Wfh = Wel + 128 * WSd;
    __nv_bfloat16* Wfl = Wfh + 128 * WSd;
    __nv_bfloat16* Xh  = Wfl + 128 * WSd;
    __nv_bfloat16* Xl  = Xh + 2 * 128 * XS;
    float* bse = (float*)(Xl + 2 * 128 * XS);
    float* bsf = bse + 128;

    const int tid = threadIdx.x, l = tid & 31, wid = tid >> 5;
    const int wm = wid & 3, wn = wid >> 2, wnl = wn & 3;
    const int row0 = blockIdx.x * 128;
    const int BUF = 128 * XS;

    for (int i = tid; i < 128 * WSd; i += 1024) {
        int nn = i / WSd, k = i - nn * WSd;
        bool ok = (k < 64 && nn < HH);
        float v1 = ok ? We[k * HH + nn] : 0.f;
        float v2 = ok ? Wf[k * HH + nn] : 0.f;
        __nv_bfloat16 h, lo;
        split_bf16(v1, h, lo); Weh[i] = h; Wel[i] = lo;
        split_bf16(v2, h, lo); Wfh[i] = h; Wfl[i] = lo;
    }
    if (tid < 128) bse[tid] = (tid < HH) ? be[tid] : 0.f;
    else if (tid < 256) { int c2 = tid - 128; bsf[c2] = (c2 < HH) ? bf[c2] : 0.f; }

    const __nv_bfloat16* Whw = (wn < 4) ? Weh : Wfh;
    const __nv_bfloat16* Wlw = (wn < 4) ? Wel : Wfl;

    float acc[2][4][4];
    zero_acc4(acc);

    float vreg[4];
    #pragma unroll
    for (int ii = 0; ii < 4; ii++) {
        int i = tid + ii * 1024;
        int r = i >> 5, kk = i & 31;
        int row = row0 + r;
        vreg[ii] = (row < NN) ? X[(size_t)row * 64 + kk] : 0.f;
    }
    #pragma unroll
    for (int ii = 0; ii < 4; ii++) {
        int i = tid + ii * 1024;
        int r = i >> 5, kk = i & 31;
        __nv_bfloat16 h, lo; split_bf16(vreg[ii], h, lo);
        Xh[r * XS + kk] = h; Xl[r * XS + kk] = lo;
    }
    __syncthreads();

    #pragma unroll
    for (int c = 0; c < 2; c++) {
        if (c == 0) {
            #pragma unroll
            for (int ii = 0; ii < 4; ii++) {
                int i = tid + ii * 1024;
                int r = i >> 5, kk = i & 31;
                int row = row0 + r;
                vreg[ii] = (row < NN) ? X[(size_t)row * 64 + 32 + kk] : 0.f;
            }
        }
        const __nv_bfloat16* xh = Xh + (c & 1) * BUF;
        const __nv_bfloat16* xl = Xl + (c & 1) * BUF;
        const int c0 = c * 32;
        #pragma unroll
        for (int ks = 0; ks < 2; ks++) {
            const int kb = ks * 16;
            #pragma unroll
            for (int mt = 0; mt < 2; mt++) {
                int r  = wm * 32 + mt * 16 + (l >> 2);
                int kk = kb + ((l & 3) << 1);
                uint32_t a0 = *(const uint32_t*)&xh[r * XS + kk];
                uint32_t a1 = *(const uint32_t*)&xh[(r + 8) * XS + kk];
                uint32_t a2 = *(const uint32_t*)&xh[r * XS + kk + 8];
                uint32_t a3 = *(const uint32_t*)&xh[(r + 8) * XS + kk + 8];
                uint32_t b0 = *(const uint32_t*)&xl[r * XS + kk];
                uint32_t b1 = *(const uint32_t*)&xl[(r + 8) * XS + kk];
                uint32_t b2 = *(const uint32_t*)&xl[r * XS + kk + 8];
                uint32_t b3 = *(const uint32_t*)&xl[(r + 8) * XS + kk + 8];
                #pragma unroll
                for (int nt = 0; nt < 4; nt++) {
                    int nn2 = wnl * 32 + nt * 8 + (l >> 2);
                    int kg  = c0 + kb + ((l & 3) << 1);
                    uint32_t bh0 = *(const uint32_t*)&Whw[nn2 * WSd + kg];
                    uint32_t bh1 = *(const uint32_t*)&Whw[nn2 * WSd + kg + 8];
                    uint32_t bl0 = *(const uint32_t*)&Wlw[nn2 * WSd + kg];
                    uint32_t bl1 = *(const uint32_t*)&Wlw[nn2 * WSd + kg + 8];
                    mma16816(acc[mt][nt], a0, a1, a2, a3, bh0, bh1);
                    mma16816(acc[mt][nt], a0, a1, a2, a3, bl0, bl1);
                    mma16816(acc[mt][nt], b0, b1, b2, b3, bh0, bh1);
                }
            }
        }
        if (c == 0) {
            __nv_bfloat16* dh = Xh + BUF;
            __nv_bfloat16* dl = Xl + BUF;
            #pragma unroll
            for (int ii = 0; ii < 4; ii++) {
                int i = tid + ii * 1024;
                int r = i >> 5, kk = i & 31;
                __nv_bfloat16 h, lo; split_bf16(vreg[ii], h, lo);
                dh[r * XS + kk] = h; dl[r * XS + kk] = lo;
            }
            __syncthreads();
        }
    }

    #pragma unroll
    for (int mt = 0; mt < 2; mt++) {
        #pragma unroll
        for (int nt = 0; nt < 4; nt++) {
            int colL = wnl * 32 + nt * 8 + ((l & 3) << 1);
            if (colL < HH) {
                int r   = wm * 32 + mt * 16 + (l >> 2);
                int row = row0 + r;
                if (wn < 4) {
                    float v0 = acc[mt][nt][0] + bse[colL];
                    float v1 = acc[mt][nt][1] + bse[colL + 1];
                    float v2 = acc[mt][nt][2] + bse[colL];
                    float v3 = acc[mt][nt][3] + bse[colL + 1];
                    if (row < NN)     *(float2*)&h0[(size_t)row * HH + colL]       = make_float2(v0, v1);
                    if (row + 8 < NN) *(float2*)&h0[(size_t)(row + 8) * HH + colL] = make_float2(v2, v3);
                } else {
                    float v0 = fmaxf(acc[mt][nt][0] + bsf[colL], 0.f);
                    float v1 = fmaxf(acc[mt][nt][1] + bsf[colL + 1], 0.f);
                    float v2 = fmaxf(acc[mt][nt][2] + bsf[colL], 0.f);
                    float v3 = fmaxf(acc[mt][nt][3] + bsf[colL + 1], 0.f);
                    if (row < NN)     *(__half2*)&m1[(size_t)row * HH + colL]       = __floats2half2_rn(v0, v1);
                    if (row + 8 < NN) *(__half2*)&m1[(size_t)(row + 8) * HH + colL] = __floats2half2_rn(v2, v3);
                }
            }
        }
    }
}

// ================= pool2 GEMM (512 thr, 2 blocks/SM, block offset) =================
__global__ __launch_bounds__(512, 2) void gemm_pool2(
        const float* __restrict__ X, const float* __restrict__ W,
        const float* __restrict__ b, __half* __restrict__ Y, int blk0) {
    const int WS = 136;
    extern __shared__ char sh[];
    __nv_bfloat16* Wh = (__nv_bfloat16*)sh;
    __nv_bfloat16* Wl = Wh + 128 * WS;
    __nv_bfloat16* Xh = Wl + 128 * WS;
    __nv_bfloat16* Xl = Xh + 2 * 128 * XS;
    float* bs = (float*)(Xl + 2 * 128 * XS);

    const int tid = threadIdx.x, l = tid & 31, wid = tid >> 5;
    const int wm = wid & 3, wn = wid >> 2;
    const int row0 = (blk0 + blockIdx.x) * 128;

    stage_W<108, WS, 512>(W, Wh, Wl, tid);
    if (tid < 128) bs[tid] = (tid < HH) ? b[tid] : 0.f;

    float acc[2][4][4];
    zero_acc4(acc);
    run_mainloop<128>(Wh, Wl, WS, Xh, Xl, acc, tid, SrcRow108{X, row0});

    #pragma unroll
    for (int mt = 0; mt < 2; mt++) {
        #pragma unroll
        for (int nt = 0; nt < 4; nt++) {
            int col = wn * 32 + nt * 8 + ((l & 3) << 1);
            if (col < HH) {
                int r   = wm * 32 + mt * 16 + (l >> 2);
                int row = row0 + r;
                float v0 = fmaxf(acc[mt][nt][0] + bs[col], 0.f);
                float v1 = fmaxf(acc[mt][nt][1] + bs[col + 1], 0.f);
                float v2 = fmaxf(acc[mt][nt][2] + bs[col], 0.f);
                float v3 = fmaxf(acc[mt][nt][3] + bs[col + 1], 0.f);
                if (row < NN)     *(__half2*)&Y[(size_t)row * HH + col]       = __floats2half2_rn(v0, v1);
                if (row + 8 < NN) *(__half2*)&Y[(size_t)(row + 8) * HH + col] = __floats2half2_rn(v2, v3);
            }
        }
    }
}

// ================= fused node apply (1024 threads, 32 warps, block offset) =========
template<bool POOL>
__global__ __launch_bounds__(1024) void mma_napply(
        const float* __restrict__ Hin, const __half* __restrict__ aggh,
        const float* __restrict__ W, const float* __restrict__ b,
        float* __restrict__ Hout, const int* __restrict__ gid,
        float* __restrict__ s, int blk0) {
    const int WS = 232;
    extern __shared__ char sh[];
    __nv_bfloat16* Wh = (__nv_bfloat16*)sh;
    __nv_bfloat16* Wl = Wh + 128 * WS;
    __nv_bfloat16* Xh = Wl + 128 * WS;
    __nv_bfloat16* Xl = Xh + 2 * 128 * XS;
    float* bs  = (float*)(Xl + 2 * 128 * XS);
    int*   gds = (int*)(bs + 128);
    float* epi = (float*)sh;

    const int tid = threadIdx.x, l = tid & 31, wid = tid >> 5;
    const int wm = wid & 3, wn = wid >> 2;
    const int row0 = (blk0 + blockIdx.x) * 128;

    stage_W<216, WS, 1024>(W, Wh, Wl, tid);
    if (tid < 128) {
        bs[tid] = (tid < HH) ? b[tid] : 0.f;
        if (POOL) gds[tid] = (row0 + tid < NN) ? gid[row0 + tid] : -1;
    }

    float acc[2][2][4];
    zero_acc2(acc);
    run_mainloop_w32<224>(Wh, Wl, WS, Xh, Xl, acc, tid, SrcHinAgg{Hin, aggh, row0});

    __syncthreads();
    #pragma unroll
    for (int mt = 0; mt < 2; mt++) {
        #pragma unroll
        for (int nt = 0; nt < 2; nt++) {
            int col = wn * 16 + nt * 8 + ((l & 3) << 1);
            int r   = wm * 32 + mt * 16 + (l >> 2);
            *(float2*)&epi[r * ES + col] =
                make_float2(acc[mt][nt][0] + bs[col], acc[mt][nt][1] + bs[col + 1]);
            *(float2*)&epi[(r + 8) * ES + col] =
                make_float2(acc[mt][nt][2] + bs[col], acc[mt][nt][3] + bs[col + 1]);
        }
    }
    __syncthreads();

    #pragma unroll
    for (int rr = 0; rr < 4; rr++) {
        int r = wid * 4 + rr;
        int row = row0 + r;
        if (row >= NN) continue;
        float v[4]; float sn = 0.f;
        #pragma unroll
        for (int j = 0; j < 4; j++) {
            int c = l + 32 * j;
            v[j] = (c < HH) ? epi[r * ES + c] : 0.f;
            sn += v[j] * v[j];
        }
        #pragma unroll
        for (int off2 = 16; off2 > 0; off2 >>= 1)
            sn += __shfl_xor_sync(0xffffffffu, sn, off2);
        float inv = 1.f / fmaxf(sqrtf(sn), 1e-12f);
        #pragma unroll
        for (int j = 0; j < 4; j++) {
            int c = l + 32 * j;
            if (c < HH) {
                float o = Hin[(size_t)row * HH + c] + fmaxf(v[j] * inv, 0.f);
                if (POOL) epi[r * ES + c] = o;
                else      Hout[(size_t)row * HH + c] = o;
            }
        }
    }

    if (POOL) {
        __syncthreads();
        int col = tid & 127, seg = tid >> 7;
        if (col < HH) {
            float a = 0.f; int curg = -1;
            #pragma unroll 4
            for (int r = seg * 16; r < seg * 16 + 16; r++) {
                int g = gds[r];
                if (g < 0) break;
                if (g != curg) {
                    if (curg >= 0) atomicAdd(&s[curg * HH + col], a);
                    curg = g; a = 0.f;
                }
                a += epi[r * ES + col];
            }
            if (curg >= 0) atomicAdd(&s[curg * HH + col], a);
        }
    }
}

// ================= weight fusion =================
__global__ __launch_bounds__(256) void fuse_w(
        const float* __restrict__ We, const float* __restrict__ be,
        const float* __restrict__ Wp, const float* __restrict__ bp,
        float* __restrict__ Wf, float* __restrict__ bf) {
    __shared__ float sWp[HH * HH];
    for (int i = threadIdx.x; i < HH * HH; i += 256) sWp[i] = Wp[i];
    __syncthreads();
    int t = blockIdx.x * 256 + threadIdx.x;
    if (t < 64 * HH) {
        int i = t / HH, j = t - (t / HH) * HH;
        const float* we = We + i * HH;
        float s0 = 0.f, s1 = 0.f;
        #pragma unroll 4
        for (int k = 0; k < HH; k += 2) {
            s0 = fmaf(we[k],     sWp[k * HH + j],       s0);
            s1 = fmaf(we[k + 1], sWp[(k + 1) * HH + j], s1);
        }
        Wf[t] = s0 + s1;
    } else if (t < 64 * HH + HH) {
        int j = t - 64 * HH;
        float s0 = bp[j], s1 = 0.f;
        #pragma unroll 4
        for (int k = 0; k < HH; k += 2) {
            s0 = fmaf(be[k],     sWp[k * HH + j],       s0);
            s1 = fmaf(be[k + 1], sWp[(k + 1) * HH + j], s1);
        }
        bf[j] = s0 + s1;
    }
}

// ================= graph prep =================
__global__ void deg_cnt_kernel(const int* __restrict__ dst, const int* __restrict__ gid,
                               int* __restrict__ degi, float* __restrict__ cnt) {
    int tk = blockIdx.x * blockDim.x + threadIdx.x;
    if (tk < EE) atomicAdd(&degi[dst[tk]], 1);
    if (tk < NN) atomicAdd(&cnt[gid[tk]], 1.f);
}

__global__ void scan_block(const int* __restrict__ degi, int* __restrict__ off,
                           int* __restrict__ cur) {
    __shared__ int wt[32];
    const int PER = 49;
    int t = threadIdx.x, lane = t & 31, w = t >> 5;
    int base = t * PER;
    int sum = 0;
    for (int j = 0; j < PER; j++) {
        int idx = base + j;
        if (idx < NN) sum += degi[idx];
    }
    int v = sum;
    #pragma unroll
    for (int d = 1; d < 32; d <<= 1) {
        int u = __shfl_up_sync(0xffffffffu, v, d);
        if (lane >= d) v += u;
    }
    if (lane == 31) wt[w] = v;
    __syncthreads();
    if (w == 0) {
        int x = wt[lane];
        #pragma unroll
        for (int d = 1; d < 32; d <<= 1) {
            int u = __shfl_up_sync(0xffffffffu, x, d);
            if (lane >= d) x += u;
        }
        wt[lane] = x;
    }
    __syncthreads();
    int run = v - sum + (w > 0 ? wt[w - 1] : 0);
    for (int j = 0; j < PER; j++) {
        int idx = base + j;
        if (idx < NN) {
            int d0 = degi[idx];
            off[idx] = run;
            cur[idx] = run;
            run += d0;
        }
    }
}

__global__ void csr_fill(const int* __restrict__ src, const int* __restrict__ dst,
                         int* __restrict__ cur, int* __restrict__ csr) {
    int e = blockIdx.x * blockDim.x + threadIdx.x;
    if (e < EE) {
        int d = dst[e];
        int pidx = atomicAdd(&cur[d], 1);
        csr[pidx] = src[e];
    }
}

// ===== gather over node range [n0, n1): one warp per node; c -> fp16; unroll 8 =====
__global__ void gather_agg(const __half* __restrict__ m, const int* __restrict__ off,
                           const int* __restrict__ csr, __half* __restrict__ aggh,
                           int n0, int n1) {
    int w = n0 + ((blockIdx.x * blockDim.x + threadIdx.x) >> 5);
    int lane = threadIdx.x & 31;
    if (w >= n1 || lane >= CH4) return;
    int s0 = off[w];
    int s1 = (w + 1 < NN) ? off[w + 1] : EE;
    float4 a0 = make_float4(0.f,0.f,0.f,0.f), a1 = a0, a2 = a0, a3 = a0;
    int j = s0;
    for (; j + 7 < s1; j += 8) {
        int idx[8];
        #pragma unroll
        for (int u = 0; u < 8; u++) idx[u] = csr[j + u];
        uint2 q[8];
        #pragma unroll
        for (int u = 0; u < 8; u++)
            q[u] = *(const uint2*)(m + (size_t)idx[u] * HH + lane * 4);
        #pragma unroll
        for (int u = 0; u < 8; u++) {
            float2 f0 = __half22float2(*(__half2*)&q[u].x);
            float2 f1 = __half22float2(*(__half2*)&q[u].y);
            float4& a = (u & 3) == 0 ? a0 : (u & 3) == 1 ? a1 : (u & 3) == 2 ? a2 : a3;
            a.x += f0.x; a.y += f0.y; a.z += f1.x; a.w += f1.y;
        }
    }
    for (; j < s1; j++) {
        int i0 = csr[j];
        uint2 q0 = *(const uint2*)(m + (size_t)i0 * HH + lane * 4);
        float2 f0 = __half22float2(*(__half2*)&q0.x);
        float2 f1 = __half22float2(*(__half2*)&q0.y);
        a0.x += f0.x; a0.y += f0.y; a0.z += f1.x; a0.w += f1.y;
    }
    float inv = 1.f / fmaxf((float)(s1 - s0), 1.f);
    a0.x = (a0.x + a1.x + a2.x + a3.x) * inv;
    a0.y = (a0.y + a1.y + a2.y + a3.y) * inv;
    a0.z = (a0.z + a1.z + a2.z + a3.z) * inv;
    a0.w = (a0.w + a1.w + a2.w + a3.w) * inv;
    __half2 o0 = __floats2half2_rn(a0.x, a0.y);
    __half2 o1 = __floats2half2_rn(a0.z, a0.w);
    *(__half2*)&aggh[(size_t)w * HH + lane * 4]     = o0;
    *(__half2*)&aggh[(size_t)w * HH + lane * 4 + 2] = o1;
}

// ================= readout finalize =================
__global__ void finalize(const float* __restrict__ s, const float* __restrict__ cnt,
                         float* __restrict__ out) {
    int tk = blockIdx.x * blockDim.x + threadIdx.x;
    if (tk < GG * HH) {
        int g = tk / HH;
        out[tk] = s[tk] / fmaxf(cnt[g], 1.f);
    }
}

// ================= launch =================
extern "C" void kernel_launch(void* const* d_in, const int* in_sizes, int n_in,
                              void* d_out, int out_size) {
    const float* nodes_feat = (const float*)d_in[0];
    const int*   src  = (const int*)d_in[4];
    const int*   dst  = (const int*)d_in[5];
    const int*   gid  = (const int*)d_in[6];
    const float* W_emb = (const float*)d_in[7];
    const float* b_emb = (const float*)d_in[8];
    const float* Wp1   = (const float*)d_in[9];
    const float* bp1   = (const float*)d_in[10];
    const float* Wn1   = (const float*)d_in[11];
    const float* bn1   = (const float*)d_in[12];
    const float* Wp2   = (const float*)d_in[13];
    const float* bp2   = (const float*)d_in[14];
    const float* Wn2   = (const float*)d_in[15];
    const float* bn2   = (const float*)d_in[16];
    float* out = (float*)d_out;

    float *p_h0, *p_h1, *p_s, *p_cnt, *p_wf, *p_bf;
    __half *p_m, *p_aggh;
    int *p_degi, *p_off, *p_cur, *p_csr;
    cudaGetSymbolAddress((void**)&p_h0,   g_h0);
    cudaGetSymbolAddress((void**)&p_h1,   g_h1);
    cudaGetSymbolAddress((void**)&p_m,    g_m);
    cudaGetSymbolAddress((void**)&p_aggh, g_aggh);
    cudaGetSymbolAddress((void**)&p_s,    g_s);
    cudaGetSymbolAddress((void**)&p_cnt,  g_cnt);
    cudaGetSymbolAddress((void**)&p_wf,   g_wf);
    cudaGetSymbolAddress((void**)&p_bf,   g_bf);
    cudaGetSymbolAddress((void**)&p_degi, g_degi);
    cudaGetSymbolAddress((void**)&p_off,  g_off);
    cudaGetSymbolAddress((void**)&p_cur,  g_cur);
    cudaGetSymbolAddress((void**)&p_csr,  g_csr);

    const int smem_dual = 4*(128*72*2) + 2*(2*128*XS*2) + 1024;   // 115,712
    const int smem_pool = 2*(128*136*2) + 2*(2*128*XS*2) + 512;   // 111,104
    const int smem_na   = 2*(128*232*2) + 2*(2*128*XS*2) + 1024;  // 160,768
    cudaFuncSetAttribute(gemm_dual,         cudaFuncAttributeMaxDynamicSharedMemorySize, smem_dual);
    cudaFuncSetAttribute(gemm_pool2,        cudaFuncAttributeMaxDynamicSharedMemorySize, smem_pool);
    cudaFuncSetAttribute(mma_napply<false>, cudaFuncAttributeMaxDynamicSharedMemorySize, smem_na);
    cudaFuncSetAttribute(mma_napply<true>,  cudaFuncAttributeMaxDynamicSharedMemorySize, smem_na);

    const int NBB = NB - NBA;   // 195

    // fork: fuse_w (s3) and CSR chain (s2) start immediately
    cudaEventRecord(g_aux.fork, 0);
    cudaStreamWaitEvent(g_aux.s3, g_aux.fork, 0);
    cudaStreamWaitEvent(g_aux.s2, g_aux.fork, 0);

    // s3: weight folding
    fuse_w<<<28, 256, 0, g_aux.s3>>>(W_emb, b_emb, Wp1, bp1, p_wf, p_bf);
    cudaEventRecord(g_aux.fw, g_aux.s3);

    // s2: CSR chain
    cudaMemsetAsync(p_degi, 0, (size_t)NN * sizeof(int), g_aux.s2);
    cudaMemsetAsync(p_cnt,  0, (size_t)GG * sizeof(float), g_aux.s2);
    deg_cnt_kernel<<<(EE + 255) / 256, 256, 0, g_aux.s2>>>(dst, gid, p_degi, p_cnt);
    scan_block<<<1, 1024, 0, g_aux.s2>>>(p_degi, p_off, p_cur);
    csr_fill<<<(EE + 255) / 256, 256, 0, g_aux.s2>>>(src, dst, p_cur, p_csr);
    cudaEventRecord(g_aux.csrdone, g_aux.s2);

    // default: readout zero-init, then dual
    cudaMemsetAsync(p_s, 0, (size_t)GG * HH * sizeof(float));
    cudaStreamWaitEvent(0, g_aux.fw, 0);
    gemm_dual<<<NB, 1024, smem_dual>>>(nodes_feat, W_emb, b_emb, p_wf, p_bf, p_h0, p_m);
    cudaEventRecord(g_aux.duald, 0);

    // layer 1, half B on s2 (ordered after csr_fill in-stream; wait for m)
    cudaStreamWaitEvent(g_aux.s2, g_aux.duald, 0);
    gather_agg<<<((NN - NSPLIT) * 32 + 255) / 256, 256, 0, g_aux.s2>>>(p_m, p_off, p_csr, p_aggh, NSPLIT, NN);
    mma_napply<false><<<NBB, 1024, smem_na, g_aux.s2>>>(p_h0, p_aggh, Wn1, bn1, p_h1, nullptr, nullptr, NBA);
    gemm_pool2<<<NBB, 512, smem_pool, g_aux.s2>>>(p_h1, Wp2, bp2, p_m, NBA);
    cudaEventRecord(g_aux.evB, g_aux.s2);

    // layer 1, half A on default (waits csr done)
    cudaStreamWaitEvent(0, g_aux.csrdone, 0);
    gather_agg<<<(NSPLIT * 32 + 255) / 256, 256>>>(p_m, p_off, p_csr, p_aggh, 0, NSPLIT);
    mma_napply<false><<<NBA, 1024, smem_na>>>(p_h0, p_aggh, Wn1, bn1, p_h1, nullptr, nullptr, 0);
    gemm_pool2<<<NBA, 512, smem_pool>>>(p_h1, Wp2, bp2, p_m, 0);

    // join halves, then full layer 2 + fused readout
    cudaStreamWaitEvent(0, g_aux.evB, 0);
    gather_agg<<<(NN * 32 + 255) / 256, 256>>>(p_m, p_off, p_csr, p_aggh, 0, NN);
    mma_napply<true><<<NB, 1024, smem_na>>>(p_h1, p_aggh, Wn2, bn2, nullptr, gid, p_s, 0);
    finalize<<<(GG * HH + 127) / 128, 128>>>(p_s, p_cnt, out);
}

// round 16
// speedup vs baseline: 1.2761x; 1.0058x over previous
#include <cuda_runtime.h>
#include <cuda_bf16.h>
#include <cuda_fp16.h>
#include <math.h>
#include <stdint.h>

#define NN  50000
#define EE  800000
#define GG  128
#define HH  108
#define CH4 27
#define XS  40     // X smem k-stride (bf16)
#define ES  136    // fp32 epilogue row stride
#define NB  391    // row blocks of 128
#define NBA 196    // half A blocks (rows [0, 25088))
#define NSPLIT (NBA*128)

// ---------------- scratch (no allocations allowed) ----------------
__device__ __align__(16) float  g_h0 [NN*HH];
__device__ __align__(16) float  g_h1 [NN*HH];
__device__ __align__(16) __half g_m  [NN*HH];
__device__ __align__(16) __half g_aggh[NN*HH];
__device__ __align__(16) float  g_s  [GG*HH];
__device__ __align__(16) float  g_wf [64*HH];
__device__ float g_bf[HH];
__device__ int   g_degi[NN];
__device__ int   g_off [NN];
__device__ int   g_cur [NN];
__device__ int   g_csr [EE];
__device__ float g_cnt[GG];

// ---------------- side streams + events ----------------
struct AuxStreams {
    cudaStream_t s2, s3;
    cudaEvent_t fork, fw, csrdone, duald, evB, poolA, evB2;
    AuxStreams() {
        cudaStreamCreateWithFlags(&s2, cudaStreamNonBlocking);
        cudaStreamCreateWithFlags(&s3, cudaStreamNonBlocking);
        cudaEventCreateWithFlags(&fork,    cudaEventDisableTiming);
        cudaEventCreateWithFlags(&fw,      cudaEventDisableTiming);
        cudaEventCreateWithFlags(&csrdone, cudaEventDisableTiming);
        cudaEventCreateWithFlags(&duald,   cudaEventDisableTiming);
        cudaEventCreateWithFlags(&evB,     cudaEventDisableTiming);
        cudaEventCreateWithFlags(&poolA,   cudaEventDisableTiming);
        cudaEventCreateWithFlags(&evB2,    cudaEventDisableTiming);
    }
};
static AuxStreams g_aux;

// ---------------- mma.sync m16n8k16 bf16 -> f32 ----------------
__device__ __forceinline__ void mma16816(float* c,
        uint32_t a0, uint32_t a1, uint32_t a2, uint32_t a3,
        uint32_t b0, uint32_t b1) {
    asm volatile(
        "mma.sync.aligned.m16n8k16.row.col.f32.bf16.bf16.f32 "
        "{%0,%1,%2,%3}, {%4,%5,%6,%7}, {%8,%9}, {%0,%1,%2,%3};"
        : "+f"(c[0]), "+f"(c[1]), "+f"(c[2]), "+f"(c[3])
        : "r"(a0), "r"(a1), "r"(a2), "r"(a3), "r"(b0), "r"(b1));
}

__device__ __forceinline__ void split_bf16(float v, __nv_bfloat16& h, __nv_bfloat16& l) {
    h = __float2bfloat16(v);
    l = __float2bfloat16(v - __bfloat162float(h));
}

// stage W[K][108] -> smem transposed/split: Wh/Wl [n(128)][k(WS)] zero-padded
template<int K, int WS, int NT>
__device__ __forceinline__ void stage_W(const float* __restrict__ W,
        __nv_bfloat16* Wh, __nv_bfloat16* Wl, int tid) {
    for (int i = tid; i < 128 * WS; i += NT) {
        int nn = i / WS, k = i - nn * WS;
        float v = (k < K && nn < HH) ? W[k * HH + nn] : 0.f;
        __nv_bfloat16 h, l;
        split_bf16(v, h, l);
        Wh[i] = h; Wl[i] = l;
    }
}

// ---------------- X sources ----------------
struct SrcRow108 {
    const float* X; int row0;
    __device__ __forceinline__ float operator()(int r, int k) const {
        int row = row0 + r;
        return (row < NN && k < HH) ? X[(size_t)row * HH + k] : 0.f;
    }
};
struct SrcHinAgg {
    const float* Hin; const __half* aggh; int row0;
    __device__ __forceinline__ float operator()(int r, int k) const {
        int row = row0 + r;
        if (row >= NN) return 0.f;
        if (k < HH)  return Hin[(size_t)row * HH + k];
        if (k < 216) return __half2float(aggh[(size_t)row * HH + (k - HH)]);
        return 0.f;
    }
};

// ---------------- 512-thread mainloop (16 warps, warp tile 32x32) ----------------
template<int KPAD, typename F>
__device__ __forceinline__ void run_mainloop(
        const __nv_bfloat16* __restrict__ Wh, const __nv_bfloat16* __restrict__ Wl,
        const int WS, __nv_bfloat16* Xh, __nv_bfloat16* Xl,
        float (&acc)[2][4][4], int tid, F xsrc) {
    const int l = tid & 31, wid = tid >> 5;
    const int wm = wid & 3, wn = wid >> 2;
    const int NC = KPAD / 32;
    const int BUF = 128 * XS;
    float vreg[8];

    #pragma unroll
    for (int ii = 0; ii < 8; ii++) {
        int i = tid + ii * 512;
        vreg[ii] = xsrc(i >> 5, i & 31);
    }
    #pragma unroll
    for (int ii = 0; ii < 8; ii++) {
        int i = tid + ii * 512;
        int r = i >> 5, kk = i & 31;
        __nv_bfloat16 h, lo;
        split_bf16(vreg[ii], h, lo);
        Xh[r * XS + kk] = h; Xl[r * XS + kk] = lo;
    }
    __syncthreads();

    #pragma unroll
    for (int c = 0; c < NC; c++) {
        if (c + 1 < NC) {
            #pragma unroll
            for (int ii = 0; ii < 8; ii++) {
                int i = tid + ii * 512;
                vreg[ii] = xsrc(i >> 5, (c + 1) * 32 + (i & 31));
            }
        }
        const __nv_bfloat16* xh = Xh + (c & 1) * BUF;
        const __nv_bfloat16* xl = Xl + (c & 1) * BUF;
        const int c0 = c * 32;
        #pragma unroll
        for (int ks = 0; ks < 2; ks++) {
            const int kb = ks * 16;
            uint32_t ah[2][4], al[2][4];
            #pragma unroll
            for (int mt = 0; mt < 2; mt++) {
                int r  = wm * 32 + mt * 16 + (l >> 2);
                int kk = kb + ((l & 3) << 1);
                ah[mt][0] = *(const uint32_t*)&xh[r * XS + kk];
                ah[mt][1] = *(const uint32_t*)&xh[(r + 8) * XS + kk];
                ah[mt][2] = *(const uint32_t*)&xh[r * XS + kk + 8];
                ah[mt][3] = *(const uint32_t*)&xh[(r + 8) * XS + kk + 8];
                al[mt][0] = *(const uint32_t*)&xl[r * XS + kk];
                al[mt][1] = *(const uint32_t*)&xl[(r + 8) * XS + kk];
                al[mt][2] = *(const uint32_t*)&xl[r * XS + kk + 8];
                al[mt][3] = *(const uint32_t*)&xl[(r + 8) * XS + kk + 8];
            }
            #pragma unroll
            for (int nt = 0; nt < 4; nt++) {
                int nn2 = wn * 32 + nt * 8 + (l >> 2);
                int kg  = c0 + kb + ((l & 3) << 1);
                uint32_t bh0 = *(const uint32_t*)&Wh[nn2 * WS + kg];
                uint32_t bh1 = *(const uint32_t*)&Wh[nn2 * WS + kg + 8];
                uint32_t bl0 = *(const uint32_t*)&Wl[nn2 * WS + kg];
                uint32_t bl1 = *(const uint32_t*)&Wl[nn2 * WS + kg + 8];
                #pragma unroll
                for (int mt = 0; mt < 2; mt++) {
                    mma16816(acc[mt][nt], ah[mt][0], ah[mt][1], ah[mt][2], ah[mt][3], bh0, bh1);
                    mma16816(acc[mt][nt], ah[mt][0], ah[mt][1], ah[mt][2], ah[mt][3], bl0, bl1);
                    mma16816(acc[mt][nt], al[mt][0], al[mt][1], al[mt][2], al[mt][3], bh0, bh1);
                }
            }
        }
        if (c + 1 < NC) {
            __nv_bfloat16* dh = Xh + ((c + 1) & 1) * BUF;
            __nv_bfloat16* dl = Xl + ((c + 1) & 1) * BUF;
            #pragma unroll
            for (int ii = 0; ii < 8; ii++) {
                int i = tid + ii * 512;
                int r = i >> 5, kk = i & 31;
                __nv_bfloat16 h, lo;
                split_bf16(vreg[ii], h, lo);
                dh[r * XS + kk] = h; dl[r * XS + kk] = lo;
            }
            __syncthreads();
        }
    }
}

// ---------------- 1024-thread mainloop (32 warps, warp tile 32x16) ----------------
template<int KPAD, typename F>
__device__ __forceinline__ void run_mainloop_w32(
        const __nv_bfloat16* __restrict__ Wh, const __nv_bfloat16* __restrict__ Wl,
        const int WS, __nv_bfloat16* Xh, __nv_bfloat16* Xl,
        float (&acc)[2][2][4], int tid, F xsrc) {
    const int l = tid & 31, wid = tid >> 5;
    const int wm = wid & 3, wn = wid >> 2;
    const int NC = KPAD / 32;
    const int BUF = 128 * XS;
    float vreg[4];

    #pragma unroll
    for (int ii = 0; ii < 4; ii++) {
        int i = tid + ii * 1024;
        vreg[ii] = xsrc(i >> 5, i & 31);
    }
    #pragma unroll
    for (int ii = 0; ii < 4; ii++) {
        int i = tid + ii * 1024;
        int r = i >> 5, kk = i & 31;
        __nv_bfloat16 h, lo;
        split_bf16(vreg[ii], h, lo);
        Xh[r * XS + kk] = h; Xl[r * XS + kk] = lo;
    }
    __syncthreads();

    #pragma unroll
    for (int c = 0; c < NC; c++) {
        if (c + 1 < NC) {
            #pragma unroll
            for (int ii = 0; ii < 4; ii++) {
                int i = tid + ii * 1024;
                vreg[ii] = xsrc(i >> 5, (c + 1) * 32 + (i & 31));
            }
        }
        const __nv_bfloat16* xh = Xh + (c & 1) * BUF;
        const __nv_bfloat16* xl = Xl + (c & 1) * BUF;
        const int c0 = c * 32;
        #pragma unroll
        for (int ks = 0; ks < 2; ks++) {
            const int kb = ks * 16;
            uint32_t ah[2][4], al[2][4];
            #pragma unroll
            for (int mt = 0; mt < 2; mt++) {
                int r  = wm * 32 + mt * 16 + (l >> 2);
                int kk = kb + ((l & 3) << 1);
                ah[mt][0] = *(const uint32_t*)&xh[r * XS + kk];
                ah[mt][1] = *(const uint32_t*)&xh[(r + 8) * XS + kk];
                ah[mt][2] = *(const uint32_t*)&xh[r * XS + kk + 8];
                ah[mt][3] = *(const uint32_t*)&xh[(r + 8) * XS + kk + 8];
                al[mt][0] = *(const uint32_t*)&xl[r * XS + kk];
                al[mt][1] = *(const uint32_t*)&xl[(r + 8) * XS + kk];
                al[mt][2] = *(const uint32_t*)&xl[r * XS + kk + 8];
                al[mt][3] = *(const uint32_t*)&xl[(r + 8) * XS + kk + 8];
            }
            #pragma unroll
            for (int nt = 0; nt < 2; nt++) {
                int nn2 = wn * 16 + nt * 8 + (l >> 2);
                int kg  = c0 + kb + ((l & 3) << 1);
                uint32_t bh0 = *(const uint32_t*)&Wh[nn2 * WS + kg];
                uint32_t bh1 = *(const uint32_t*)&Wh[nn2 * WS + kg + 8];
                uint32_t bl0 = *(const uint32_t*)&Wl[nn2 * WS + kg];
                uint32_t bl1 = *(const uint32_t*)&Wl[nn2 * WS + kg + 8];
                #pragma unroll
                for (int mt = 0; mt < 2; mt++) {
                    mma16816(acc[mt][nt], ah[mt][0], ah[mt][1], ah[mt][2], ah[mt][3], bh0, bh1);
                    mma16816(acc[mt][nt], ah[mt][0], ah[mt][1], ah[mt][2], ah[mt][3], bl0, bl1);
                    mma16816(acc[mt][nt], al[mt][0], al[mt][1], al[mt][2], al[mt][3], bh0, bh1);
                }
            }
        }
        if (c + 1 < NC) {
            __nv_bfloat16* dh = Xh + ((c + 1) & 1) * BUF;
            __nv_bfloat16* dl = Xl + ((c + 1) & 1) * BUF;
            #pragma unroll
            for (int ii = 0; ii < 4; ii++) {
                int i = tid + ii * 1024;
                int r = i >> 5, kk = i & 31;
                __nv_bfloat16 h, lo;
                split_bf16(vreg[ii], h, lo);
                dh[r * XS + kk] = h; dl[r * XS + kk] = lo;
            }
            __syncthreads();
        }
    }
}

__device__ __forceinline__ void zero_acc4(float (&acc)[2][4][4]) {
    #pragma unroll
    for (int mt = 0; mt < 2; mt++)
        #pragma unroll
        for (int nt = 0; nt < 4; nt++)
            #pragma unroll
            for (int i = 0; i < 4; i++) acc[mt][nt][i] = 0.f;
}
__device__ __forceinline__ void zero_acc2(float (&acc)[2][2][4]) {
    #pragma unroll
    for (int mt = 0; mt < 2; mt++)
        #pragma unroll
        for (int nt = 0; nt < 2; nt++)
            #pragma unroll
            for (int i = 0; i < 4; i++) acc[mt][nt][i] = 0.f;
}

// ================= dual GEMM: h0 = X@We+be (fp32); m1 = relu(X@Wf+bf) (fp16) =====
__global__ __launch_bounds__(1024) void gemm_dual(
        const float* __restrict__ X,
        const float* __restrict__ We, const float* __restrict__ be,
        const float* __restrict__ Wf, const float* __restrict__ bf,
        float* __restrict__ h0, __half* __restrict__ m1) {
    const int WSd = 72;
    extern __shared__ char sh[];
    __nv_bfloat16* Weh = (__nv_bfloat16*)sh;
    __nv_bfloat16* Wel = Weh + 128 * WSd;
    __nv_bfloat16* Wfh = Wel + 128 * WSd;
    __nv_bfloat16* Wfl = Wfh + 128 * WSd;
    __nv_bfloat16* Xh  = Wfl + 128 * WSd;
    __nv_bfloat16* Xl  = Xh + 2 * 128 * XS;
    float* bse = (float*)(Xl + 2 * 128 * XS);
    float* bsf = bse + 128;

    const int tid = threadIdx.x, l = tid & 31, wid = tid >> 5;
    const int wm = wid & 3, wn = wid >> 2, wnl = wn & 3;
    const int row0 = blockIdx.x * 128;
    const int BUF = 128 * XS;

    for (int i = tid; i < 128 * WSd; i += 1024) {
        int nn = i / WSd, k = i - nn * WSd;
        bool ok = (k < 64 && nn < HH);
        float v1 = ok ? We[k * HH + nn] : 0.f;
        float v2 = ok ? Wf[k * HH + nn] : 0.f;
        __nv_bfloat16 h, lo;
        split_bf16(v1, h, lo); Weh[i] = h; Wel[i] = lo;
        split_bf16(v2, h, lo); Wfh[i] = h; Wfl[i] = lo;
    }
    if (tid < 128) bse[tid] = (tid < HH) ? be[tid] : 0.f;
    else if (tid < 256) { int c2 = tid - 128; bsf[c2] = (c2 < HH) ? bf[c2] : 0.f; }

    const __nv_bfloat16* Whw = (wn < 4) ? Weh : Wfh;
    const __nv_bfloat16* Wlw = (wn < 4) ? Wel : Wfl;

    float acc[2][4][4];
    zero_acc4(acc);

    float vreg[4];
    #pragma unroll
    for (int ii = 0; ii < 4; ii++) {
        int i = tid + ii * 1024;
        int r = i >> 5, kk = i & 31;
        int row = row0 + r;
        vreg[ii] = (row < NN) ? X[(size_t)row * 64 + kk] : 0.f;
    }
    #pragma unroll
    for (int ii = 0; ii < 4; ii++) {
        int i = tid + ii * 1024;
        int r = i >> 5, kk = i & 31;
        __nv_bfloat16 h, lo; split_bf16(vreg[ii], h, lo);
        Xh[r * XS + kk] = h; Xl[r * XS + kk] = lo;
    }
    __syncthreads();

    #pragma unroll
    for (int c = 0; c < 2; c++) {
        if (c == 0) {
            #pragma unroll
            for (int ii = 0; ii < 4; ii++) {
                int i = tid + ii * 1024;
                int r = i >> 5, kk = i & 31;
                int row = row0 + r;
                vreg[ii] = (row < NN) ? X[(size_t)row * 64 + 32 + kk] : 0.f;
            }
        }
        const __nv_bfloat16* xh = Xh + (c & 1) * BUF;
        const __nv_bfloat16* xl = Xl + (c & 1) * BUF;
        const int c0 = c * 32;
        #pragma unroll
        for (int ks = 0; ks < 2; ks++) {
            const int kb = ks * 16;
            #pragma unroll
            for (int mt = 0; mt < 2; mt++) {
                int r  = wm * 32 + mt * 16 + (l >> 2);
                int kk = kb + ((l & 3) << 1);
                uint32_t a0 = *(const uint32_t*)&xh[r * XS + kk];
                uint32_t a1 = *(const uint32_t*)&xh[(r + 8) * XS + kk];
                uint32_t a2 = *(const uint32_t*)&xh[r * XS + kk + 8];
                uint32_t a3 = *(const uint32_t*)&xh[(r + 8) * XS + kk + 8];
                uint32_t b0 = *(const uint32_t*)&xl[r * XS + kk];
                uint32_t b1 = *(const uint32_t*)&xl[(r + 8) * XS + kk];
                uint32_t b2 = *(const uint32_t*)&xl[r * XS + kk + 8];
                uint32_t b3 = *(const uint32_t*)&xl[(r + 8) * XS + kk + 8];
                #pragma unroll
                for (int nt = 0; nt < 4; nt++) {
                    int nn2 = wnl * 32 + nt * 8 + (l >> 2);
                    int kg  = c0 + kb + ((l & 3) << 1);
                    uint32_t bh0 = *(const uint32_t*)&Whw[nn2 * WSd + kg];
                    uint32_t bh1 = *(const uint32_t*)&Whw[nn2 * WSd + kg + 8];
                    uint32_t bl0 = *(const uint32_t*)&Wlw[nn2 * WSd + kg];
                    uint32_t bl1 = *(const uint32_t*)&Wlw[nn2 * WSd + kg + 8];
                    mma16816(acc[mt][nt], a0, a1, a2, a3, bh0, bh1);
                    mma16816(acc[mt][nt], a0, a1, a2, a3, bl0, bl1);
                    mma16816(acc[mt][nt], b0, b1, b2, b3, bh0, bh1);
                }
            }
        }
        if (c == 0) {
            __nv_bfloat16* dh = Xh + BUF;
            __nv_bfloat16* dl = Xl + BUF;
            #pragma unroll
            for (int ii = 0; ii < 4; ii++) {
                int i = tid + ii * 1024;
                int r = i >> 5, kk = i & 31;
                __nv_bfloat16 h, lo; split_bf16(vreg[ii], h, lo);
                dh[r * XS + kk] = h; dl[r * XS + kk] = lo;
            }
            __syncthreads();
        }
    }

    #pragma unroll
    for (int mt = 0; mt < 2; mt++) {
        #pragma unroll
        for (int nt = 0; nt < 4; nt++) {
            int colL = wnl * 32 + nt * 8 + ((l & 3) << 1);
            if (colL < HH) {
                int r   = wm * 32 + mt * 16 + (l >> 2);
                int row = row0 + r;
                if (wn < 4) {
                    float v0 = acc[mt][nt][0] + bse[colL];
                    float v1 = acc[mt][nt][1] + bse[colL + 1];
                    float v2 = acc[mt][nt][2] + bse[colL];
                    float v3 = acc[mt][nt][3] + bse[colL + 1];
                    if (row < NN)     *(float2*)&h0[(size_t)row * HH + colL]       = make_float2(v0, v1);
                    if (row + 8 < NN) *(float2*)&h0[(size_t)(row + 8) * HH + colL] = make_float2(v2, v3);
                } else {
                    float v0 = fmaxf(acc[mt][nt][0] + bsf[colL], 0.f);
                    float v1 = fmaxf(acc[mt][nt][1] + bsf[colL + 1], 0.f);
                    float v2 = fmaxf(acc[mt][nt][2] + bsf[colL], 0.f);
                    float v3 = fmaxf(acc[mt][nt][3] + bsf[colL + 1], 0.f);
                    if (row < NN)     *(__half2*)&m1[(size_t)row * HH + colL]       = __floats2half2_rn(v0, v1);
                    if (row + 8 < NN) *(__half2*)&m1[(size_t)(row + 8) * HH + colL] = __floats2half2_rn(v2, v3);
                }
            }
        }
    }
}

// ================= pool2 GEMM (512 thr, 2 blocks/SM, block offset) =================
__global__ __launch_bounds__(512, 2) void gemm_pool2(
        const float* __restrict__ X, const float* __restrict__ W,
        const float* __restrict__ b, __half* __restrict__ Y, int blk0) {
    const int WS = 136;
    extern __shared__ char sh[];
    __nv_bfloat16* Wh = (__nv_bfloat16*)sh;
    __nv_bfloat16* Wl = Wh + 128 * WS;
    __nv_bfloat16* Xh = Wl + 128 * WS;
    __nv_bfloat16* Xl = Xh + 2 * 128 * XS;
    float* bs = (float*)(Xl + 2 * 128 * XS);

    const int tid = threadIdx.x, l = tid & 31, wid = tid >> 5;
    const int wm = wid & 3, wn = wid >> 2;
    const int row0 = (blk0 + blockIdx.x) * 128;

    stage_W<108, WS, 512>(W, Wh, Wl, tid);
    if (tid < 128) bs[tid] = (tid < HH) ? b[tid] : 0.f;

    float acc[2][4][4];
    zero_acc4(acc);
    run_mainloop<128>(Wh, Wl, WS, Xh, Xl, acc, tid, SrcRow108{X, row0});

    #pragma unroll
    for (int mt = 0; mt < 2; mt++) {
        #pragma unroll
        for (int nt = 0; nt < 4; nt++) {
            int col = wn * 32 + nt * 8 + ((l & 3) << 1);
            if (col < HH) {
                int r   = wm * 32 + mt * 16 + (l >> 2);
                int row = row0 + r;
                float v0 = fmaxf(acc[mt][nt][0] + bs[col], 0.f);
                float v1 = fmaxf(acc[mt][nt][1] + bs[col + 1], 0.f);
                float v2 = fmaxf(acc[mt][nt][2] + bs[col], 0.f);
                float v3 = fmaxf(acc[mt][nt][3] + bs[col + 1], 0.f);
                if (row < NN)     *(__half2*)&Y[(size_t)row * HH + col]       = __floats2half2_rn(v0, v1);
                if (row + 8 < NN) *(__half2*)&Y[(size_t)(row + 8) * HH + col] = __floats2half2_rn(v2, v3);
            }
        }
    }
}

// ================= fused node apply (1024 threads, 32 warps, block offset) =========
template<bool POOL>
__global__ __launch_bounds__(1024) void mma_napply(
        const float* __restrict__ Hin, const __half* __restrict__ aggh,
        const float* __restrict__ W, const float* __restrict__ b,
        float* __restrict__ Hout, const int* __restrict__ gid,
        float* __restrict__ s, int blk0) {
    const int WS = 232;
    extern __shared__ char sh[];
    __nv_bfloat16* Wh = (__nv_bfloat16*)sh;
    __nv_bfloat16* Wl = Wh + 128 * WS;
    __nv_bfloat16* Xh = Wl + 128 * WS;
    __nv_bfloat16* Xl = Xh + 2 * 128 * XS;
    float* bs  = (float*)(Xl + 2 * 128 * XS);
    int*   gds = (int*)(bs + 128);
    float* epi = (float*)sh;

    const int tid = threadIdx.x, l = tid & 31, wid = tid >> 5;
    const int wm = wid & 3, wn = wid >> 2;
    const int row0 = (blk0 + blockIdx.x) * 128;

    stage_W<216, WS, 1024>(W, Wh, Wl, tid);
    if (tid < 128) {
        bs[tid] = (tid < HH) ? b[tid] : 0.f;
        if (POOL) gds[tid] = (row0 + tid < NN) ? gid[row0 + tid] : -1;
    }

    float acc[2][2][4];
    zero_acc2(acc);
    run_mainloop_w32<224>(Wh, Wl, WS, Xh, Xl, acc, tid, SrcHinAgg{Hin, aggh, row0});

    __syncthreads();
    #pragma unroll
    for (int mt = 0; mt < 2; mt++) {
        #pragma unroll
        for (int nt = 0; nt < 2; nt++) {
            int col = wn * 16 + nt * 8 + ((l & 3) << 1);
            int r   = wm * 32 + mt * 16 + (l >> 2);
            *(float2*)&epi[r * ES + col] =
                make_float2(acc[mt][nt][0] + bs[col], acc[mt][nt][1] + bs[col + 1]);
            *(float2*)&epi[(r + 8) * ES + col] =
                make_float2(acc[mt][nt][2] + bs[col], acc[mt][nt][3] + bs[col + 1]);
        }
    }
    __syncthreads();

    #pragma unroll
    for (int rr = 0; rr < 4; rr++) {
        int r = wid * 4 + rr;
        int row = row0 + r;
        if (row >= NN) continue;
        float v[4]; float sn = 0.f;
        #pragma unroll
        for (int j = 0; j < 4; j++) {
            int c = l + 32 * j;
            v[j] = (c < HH) ? epi[r * ES + c] : 0.f;
            sn += v[j] * v[j];
        }
        #pragma unroll
        for (int off2 = 16; off2 > 0; off2 >>= 1)
            sn += __shfl_xor_sync(0xffffffffu, sn, off2);
        float inv = 1.f / fmaxf(sqrtf(sn), 1e-12f);
        #pragma unroll
        for (int j = 0; j < 4; j++) {
            int c = l + 32 * j;
            if (c < HH) {
                float o = Hin[(size_t)row * HH + c] + fmaxf(v[j] * inv, 0.f);
                if (POOL) epi[r * ES + c] = o;
                else      Hout[(size_t)row * HH + c] = o;
            }
        }
    }

    if (POOL) {
        __syncthreads();
        int col = tid & 127, seg = tid >> 7;
        if (col < HH) {
            float a = 0.f; int curg = -1;
            #pragma unroll 4
            for (int r = seg * 16; r < seg * 16 + 16; r++) {
                int g = gds[r];
                if (g < 0) break;
                if (g != curg) {
                    if (curg >= 0) atomicAdd(&s[curg * HH + col], a);
                    curg = g; a = 0.f;
                }
                a += epi[r * ES + col];
            }
            if (curg >= 0) atomicAdd(&s[curg * HH + col], a);
        }
    }
}

// ================= weight fusion =================
__global__ __launch_bounds__(256) void fuse_w(
        const float* __restrict__ We, const float* __restrict__ be,
        const float* __restrict__ Wp, const float* __restrict__ bp,
        float* __restrict__ Wf, float* __restrict__ bf) {
    __shared__ float sWp[HH * HH];
    for (int i = threadIdx.x; i < HH * HH; i += 256) sWp[i] = Wp[i];
    __syncthreads();
    int t = blockIdx.x * 256 + threadIdx.x;
    if (t < 64 * HH) {
        int i = t / HH, j = t - (t / HH) * HH;
        const float* we = We + i * HH;
        float s0 = 0.f, s1 = 0.f;
        #pragma unroll 4
        for (int k = 0; k < HH; k += 2) {
            s0 = fmaf(we[k],     sWp[k * HH + j],       s0);
            s1 = fmaf(we[k + 1], sWp[(k + 1) * HH + j], s1);
        }
        Wf[t] = s0 + s1;
    } else if (t < 64 * HH + HH) {
        int j = t - 64 * HH;
        float s0 = bp[j], s1 = 0.f;
        #pragma unroll 4
        for (int k = 0; k < HH; k += 2) {
            s0 = fmaf(be[k],     sWp[k * HH + j],       s0);
            s1 = fmaf(be[k + 1], sWp[(k + 1) * HH + j], s1);
        }
        bf[j] = s0 + s1;
    }
}

// ================= graph prep =================
__global__ void deg_cnt_kernel(const int* __restrict__ dst, const int* __restrict__ gid,
                               int* __restrict__ degi, float* __restrict__ cnt) {
    int tk = blockIdx.x * blockDim.x + threadIdx.x;
    if (tk < EE) atomicAdd(&degi[dst[tk]], 1);
    if (tk < NN) atomicAdd(&cnt[gid[tk]], 1.f);
}

__global__ void scan_block(const int* __restrict__ degi, int* __restrict__ off,
                           int* __restrict__ cur) {
    __shared__ int wt[32];
    const int PER = 49;
    int t = threadIdx.x, lane = t & 31, w = t >> 5;
    int base = t * PER;
    int sum = 0;
    for (int j = 0; j < PER; j++) {
        int idx = base + j;
        if (idx < NN) sum += degi[idx];
    }
    int v = sum;
    #pragma unroll
    for (int d = 1; d < 32; d <<= 1) {
        int u = __shfl_up_sync(0xffffffffu, v, d);
        if (lane >= d) v += u;
    }
    if (lane == 31) wt[w] = v;
    __syncthreads();
    if (w == 0) {
        int x = wt[lane];
        #pragma unroll
        for (int d = 1; d < 32; d <<= 1) {
            int u = __shfl_up_sync(0xffffffffu, x, d);
            if (lane >= d) x += u;
        }
        wt[lane] = x;
    }
    __syncthreads();
    int run = v - sum + (w > 0 ? wt[w - 1] : 0);
    for (int j = 0; j < PER; j++) {
        int idx = base + j;
        if (idx < NN) {
            int d0 = degi[idx];
            off[idx] = run;
            cur[idx] = run;
            run += d0;
        }
    }
}

__global__ void csr_fill(const int* __restrict__ src, const int* __restrict__ dst,
                         int* __restrict__ cur, int* __restrict__ csr) {
    int e = blockIdx.x * blockDim.x + threadIdx.x;
    if (e < EE) {
        int d = dst[e];
        int pidx = atomicAdd(&cur[d], 1);
        csr[pidx] = src[e];
    }
}

// ===== gather over node range [n0, n1): one warp per node; c -> fp16; unroll 8 =====
__global__ void gather_agg(const __half* __restrict__ m, const int* __restrict__ off,
                           const int* __restrict__ csr, __half* __restrict__ aggh,
                           int n0, int n1) {
    int w = n0 + ((blockIdx.x * blockDim.x + threadIdx.x) >> 5);
    int lane = threadIdx.x & 31;
    if (w >= n1 || lane >= CH4) return;
    int s0 = off[w];
    int s1 = (w + 1 < NN) ? off[w + 1] : EE;
    float4 a0 = make_float4(0.f,0.f,0.f,0.f), a1 = a0, a2 = a0, a3 = a0;
    int j = s0;
    for (; j + 7 < s1; j += 8) {
        int idx[8];
        #pragma unroll
        for (int u = 0; u < 8; u++) idx[u] = csr[j + u];
        uint2 q[8];
        #pragma unroll
        for (int u = 0; u < 8; u++)
            q[u] = *(const uint2*)(m + (size_t)idx[u] * HH + lane * 4);
        #pragma unroll
        for (int u = 0; u < 8; u++) {
            float2 f0 = __half22float2(*(__half2*)&q[u].x);
            float2 f1 = __half22float2(*(__half2*)&q[u].y);
            float4& a = (u & 3) == 0 ? a0 : (u & 3) == 1 ? a1 : (u & 3) == 2 ? a2 : a3;
            a.x += f0.x; a.y += f0.y; a.z += f1.x; a.w += f1.y;
        }
    }
    for (; j < s1; j++) {
        int i0 = csr[j];
        uint2 q0 = *(const uint2*)(m + (size_t)i0 * HH + lane * 4);
        float2 f0 = __half22float2(*(__half2*)&q0.x);
        float2 f1 = __half22float2(*(__half2*)&q0.y);
        a0.x += f0.x; a0.y += f0.y; a0.z += f1.x; a0.w += f1.y;
    }
    float inv = 1.f / fmaxf((float)(s1 - s0), 1.f);
    a0.x = (a0.x + a1.x + a2.x + a3.x) * inv;
    a0.y = (a0.y + a1.y + a2.y + a3.y) * inv;
    a0.z = (a0.z + a1.z + a2.z + a3.z) * inv;
    a0.w = (a0.w + a1.w + a2.w + a3.w) * inv;
    __half2 o0 = __floats2half2_rn(a0.x, a0.y);
    __half2 o1 = __floats2half2_rn(a0.z, a0.w);
    *(__half2*)&aggh[(size_t)w * HH + lane * 4]     = o0;
    *(__half2*)&aggh[(size_t)w * HH + lane * 4 + 2] = o1;
}

// ================= readout finalize =================
__global__ void finalize(const float* __restrict__ s, const float* __restrict__ cnt,
                         float* __restrict__ out) {
    int tk = blockIdx.x * blockDim.x + threadIdx.x;
    if (tk < GG * HH) {
        int g = tk / HH;
        out[tk] = s[tk] / fmaxf(cnt[g], 1.f);
    }
}

// ================= launch =================
extern "C" void kernel_launch(void* const* d_in, const int* in_sizes, int n_in,
                              void* d_out, int out_size) {
    const float* nodes_feat = (const float*)d_in[0];
    const int*   src  = (const int*)d_in[4];
    const int*   dst  = (const int*)d_in[5];
    const int*   gid  = (const int*)d_in[6];
    const float* W_emb = (const float*)d_in[7];
    const float* b_emb = (const float*)d_in[8];
    const float* Wp1   = (const float*)d_in[9];
    const float* bp1   = (const float*)d_in[10];
    const float* Wn1   = (const float*)d_in[11];
    const float* bn1   = (const float*)d_in[12];
    const float* Wp2   = (const float*)d_in[13];
    const float* bp2   = (const float*)d_in[14];
    const float* Wn2   = (const float*)d_in[15];
    const float* bn2   = (const float*)d_in[16];
    float* out = (float*)d_out;

    float *p_h0, *p_h1, *p_s, *p_cnt, *p_wf, *p_bf;
    __half *p_m, *p_aggh;
    int *p_degi, *p_off, *p_cur, *p_csr;
    cudaGetSymbolAddress((void**)&p_h0,   g_h0);
    cudaGetSymbolAddress((void**)&p_h1,   g_h1);
    cudaGetSymbolAddress((void**)&p_m,    g_m);
    cudaGetSymbolAddress((void**)&p_aggh, g_aggh);
    cudaGetSymbolAddress((void**)&p_s,    g_s);
    cudaGetSymbolAddress((void**)&p_cnt,  g_cnt);
    cudaGetSymbolAddress((void**)&p_wf,   g_wf);
    cudaGetSymbolAddress((void**)&p_bf,   g_bf);
    cudaGetSymbolAddress((void**)&p_degi, g_degi);
    cudaGetSymbolAddress((void**)&p_off,  g_off);
    cudaGetSymbolAddress((void**)&p_cur,  g_cur);
    cudaGetSymbolAddress((void**)&p_csr,  g_csr);

    const int smem_dual = 4*(128*72*2) + 2*(2*128*XS*2) + 1024;   // 115,712
    const int smem_pool = 2*(128*136*2) + 2*(2*128*XS*2) + 512;   // 111,104
    const int smem_na   = 2*(128*232*2) + 2*(2*128*XS*2) + 1024;  // 160,768
    cudaFuncSetAttribute(gemm_dual,         cudaFuncAttributeMaxDynamicSharedMemorySize, smem_dual);
    cudaFuncSetAttribute(gemm_pool2,        cudaFuncAttributeMaxDynamicSharedMemorySize, smem_pool);
    cudaFuncSetAttribute(mma_napply<false>, cudaFuncAttributeMaxDynamicSharedMemorySize, smem_na);
    cudaFuncSetAttribute(mma_napply<true>,  cudaFuncAttributeMaxDynamicSharedMemorySize, smem_na);

    const int NBB = NB - NBA;   // 195

    // fork: fuse_w (s3) and CSR chain (s2) start immediately
    cudaEventRecord(g_aux.fork, 0);
    cudaStreamWaitEvent(g_aux.s3, g_aux.fork, 0);
    cudaStreamWaitEvent(g_aux.s2, g_aux.fork, 0);

    // s3: weight folding
    fuse_w<<<28, 256, 0, g_aux.s3>>>(W_emb, b_emb, Wp1, bp1, p_wf, p_bf);
    cudaEventRecord(g_aux.fw, g_aux.s3);

    // s2: CSR chain
    cudaMemsetAsync(p_degi, 0, (size_t)NN * sizeof(int), g_aux.s2);
    cudaMemsetAsync(p_cnt,  0, (size_t)GG * sizeof(float), g_aux.s2);
    deg_cnt_kernel<<<(EE + 255) / 256, 256, 0, g_aux.s2>>>(dst, gid, p_degi, p_cnt);
    scan_block<<<1, 1024, 0, g_aux.s2>>>(p_degi, p_off, p_cur);
    csr_fill<<<(EE + 255) / 256, 256, 0, g_aux.s2>>>(src, dst, p_cur, p_csr);
    cudaEventRecord(g_aux.csrdone, g_aux.s2);

    // default: readout zero-init, then dual
    cudaMemsetAsync(p_s, 0, (size_t)GG * HH * sizeof(float));
    cudaStreamWaitEvent(0, g_aux.fw, 0);
    gemm_dual<<<NB, 1024, smem_dual>>>(nodes_feat, W_emb, b_emb, p_wf, p_bf, p_h0, p_m);
    cudaEventRecord(g_aux.duald, 0);

    // ---- layer 1, half B on s2 (csr in-stream; wait dual's m) ----
    cudaStreamWaitEvent(g_aux.s2, g_aux.duald, 0);
    gather_agg<<<((NN - NSPLIT) * 32 + 255) / 256, 256, 0, g_aux.s2>>>(p_m, p_off, p_csr, p_aggh, NSPLIT, NN);
    mma_napply<false><<<NBB, 1024, smem_na, g_aux.s2>>>(p_h0, p_aggh, Wn1, bn1, p_h1, nullptr, nullptr, NBA);
    gemm_pool2<<<NBB, 512, smem_pool, g_aux.s2>>>(p_h1, Wp2, bp2, p_m, NBA);
    cudaEventRecord(g_aux.evB, g_aux.s2);

    // ---- layer 1, half A on default (waits csr done) ----
    cudaStreamWaitEvent(0, g_aux.csrdone, 0);
    gather_agg<<<(NSPLIT * 32 + 255) / 256, 256>>>(p_m, p_off, p_csr, p_aggh, 0, NSPLIT);
    mma_napply<false><<<NBA, 1024, smem_na>>>(p_h0, p_aggh, Wn1, bn1, p_h1, nullptr, nullptr, 0);
    gemm_pool2<<<NBA, 512, smem_pool>>>(p_h1, Wp2, bp2, p_m, 0);
    cudaEventRecord(g_aux.poolA, 0);

    // ---- layer 2, half B on s2 (needs BOTH pool halves: poolA cross-wait; pool B in-stream) ----
    cudaStreamWaitEvent(g_aux.s2, g_aux.poolA, 0);
    gather_agg<<<((NN - NSPLIT) * 32 + 255) / 256, 256, 0, g_aux.s2>>>(p_m, p_off, p_csr, p_aggh, NSPLIT, NN);
    mma_napply<true><<<NBB, 1024, smem_na, g_aux.s2>>>(p_h1, p_aggh, Wn2, bn2, nullptr, gid, p_s, NBA);
    cudaEventRecord(g_aux.evB2, g_aux.s2);

    // ---- layer 2, half A on default (needs pool B: evB cross-wait; pool A in-stream) ----
    cudaStreamWaitEvent(0, g_aux.evB, 0);
    gather_agg<<<(NSPLIT * 32 + 255) / 256, 256>>>(p_m, p_off, p_csr, p_aggh, 0, NSPLIT);
    mma_napply<true><<<NBA, 1024, smem_na>>>(p_h1, p_aggh, Wn2, bn2, nullptr, gid, p_s, 0);

    // join + finalize
    cudaStreamWaitEvent(0, g_aux.evB2, 0);
    finalize<<<(GG * HH + 127) / 128, 128>>>(p_s, p_cnt, out);
}

// round 17
// speedup vs baseline: 1.4325x; 1.1225x over previous
#include <cuda_runtime.h>
#include <cuda_bf16.h>
#include <cuda_fp16.h>
#include <math.h>
#include <stdint.h>

#define NN  50000
#define EE  800000
#define GG  128
#define HH  108
#define CH4 27
#define XS  40     // X smem k-stride (bf16)
#define ES  136    // fp32 epilogue row stride
#define NB  391    // row blocks of 128
#define NBA 196    // half A blocks (rows [0, 25088))
#define NSPLIT (NBA*128)

// ---------------- scratch (no allocations allowed) ----------------
__device__ __align__(16) float  g_h0 [NN*HH];
__device__ __align__(16) float  g_h1 [NN*HH];
__device__ __align__(16) __half g_m  [NN*HH];
__device__ __align__(16) __half g_aggh[NN*HH];
__device__ __align__(16) float  g_s  [GG*HH];
__device__ __align__(16) float  g_wf [64*HH];
__device__ float g_bf[HH];
__device__ int   g_degi[NN];
__device__ int   g_off [NN];
__device__ int   g_cur [NN];
__device__ int   g_csr [EE];
__device__ float g_cnt[GG];

// ---------------- side streams + events ----------------
struct AuxStreams {
    cudaStream_t s2, s3;
    cudaEvent_t fork, fw, csrdone, duald, evB, poolA, evB2;
    AuxStreams() {
        cudaStreamCreateWithFlags(&s2, cudaStreamNonBlocking);
        cudaStreamCreateWithFlags(&s3, cudaStreamNonBlocking);
        cudaEventCreateWithFlags(&fork,    cudaEventDisableTiming);
        cudaEventCreateWithFlags(&fw,      cudaEventDisableTiming);
        cudaEventCreateWithFlags(&csrdone, cudaEventDisableTiming);
        cudaEventCreateWithFlags(&duald,   cudaEventDisableTiming);
        cudaEventCreateWithFlags(&evB,     cudaEventDisableTiming);
        cudaEventCreateWithFlags(&poolA,   cudaEventDisableTiming);
        cudaEventCreateWithFlags(&evB2,    cudaEventDisableTiming);
    }
};
static AuxStreams g_aux;

// ---------------- mma.sync m16n8k16 bf16 -> f32 ----------------
__device__ __forceinline__ void mma16816(float* c,
        uint32_t a0, uint32_t a1, uint32_t a2, uint32_t a3,
        uint32_t b0, uint32_t b1) {
    asm volatile(
        "mma.sync.aligned.m16n8k16.row.col.f32.bf16.bf16.f32 "
        "{%0,%1,%2,%3}, {%4,%5,%6,%7}, {%8,%9}, {%0,%1,%2,%3};"
        : "+f"(c[0]), "+f"(c[1]), "+f"(c[2]), "+f"(c[3])
        : "r"(a0), "r"(a1), "r"(a2), "r"(a3), "r"(b0), "r"(b1));
}

__device__ __forceinline__ void split_bf16(float v, __nv_bfloat16& h, __nv_bfloat16& l) {
    h = __float2bfloat16(v);
    l = __float2bfloat16(v - __bfloat162float(h));
}

// stage W[K][108] -> smem transposed/split: Wh/Wl [n(128)][k(WS)] zero-padded
template<int K, int WS, int NT>
__device__ __forceinline__ void stage_W(const float* __restrict__ W,
        __nv_bfloat16* Wh, __nv_bfloat16* Wl, int tid) {
    for (int i = tid; i < 128 * WS; i += NT) {
        int nn = i / WS, k = i - nn * WS;
        float v = (k < K && nn < HH) ? W[k * HH + nn] : 0.f;
        __nv_bfloat16 h, l;
        split_bf16(v, h, l);
        Wh[i] = h; Wl[i] = l;
    }
}

// ---------------- X sources ----------------
struct SrcRow108 {
    const float* X; int row0;
    __device__ __forceinline__ float operator()(int r, int k) const {
        int row = row0 + r;
        return (row < NN && k < HH) ? X[(size_t)row * HH + k] : 0.f;
    }
};
struct SrcHinAgg {
    const float* Hin; const __half* aggh; int row0;
    __device__ __forceinline__ float operator()(int r, int k) const {
        int row = row0 + r;
        if (row >= NN) return 0.f;
        if (k < HH)  return Hin[(size_t)row * HH + k];
        if (k < 216) return __half2float(aggh[(size_t)row * HH + (k - HH)]);
        return 0.f;
    }
};

// ---------------- 512-thread mainloop (16 warps, warp tile 32x32) ----------------
// X kept as single bf16 (hi only); W split hi+lo => 2 MMAs per tile.
template<int KPAD, typename F>
__device__ __forceinline__ void run_mainloop(
        const __nv_bfloat16* __restrict__ Wh, const __nv_bfloat16* __restrict__ Wl,
        const int WS, __nv_bfloat16* Xh,
        float (&acc)[2][4][4], int tid, F xsrc) {
    const int l = tid & 31, wid = tid >> 5;
    const int wm = wid & 3, wn = wid >> 2;
    const int NC = KPAD / 32;
    const int BUF = 128 * XS;
    float vreg[8];

    #pragma unroll
    for (int ii = 0; ii < 8; ii++) {
        int i = tid + ii * 512;
        vreg[ii] = xsrc(i >> 5, i & 31);
    }
    #pragma unroll
    for (int ii = 0; ii < 8; ii++) {
        int i = tid + ii * 512;
        int r = i >> 5, kk = i & 31;
        Xh[r * XS + kk] = __float2bfloat16(vreg[ii]);
    }
    __syncthreads();

    #pragma unroll
    for (int c = 0; c < NC; c++) {
        if (c + 1 < NC) {
            #pragma unroll
            for (int ii = 0; ii < 8; ii++) {
                int i = tid + ii * 512;
                vreg[ii] = xsrc(i >> 5, (c + 1) * 32 + (i & 31));
            }
        }
        const __nv_bfloat16* xh = Xh + (c & 1) * BUF;
        const int c0 = c * 32;
        #pragma unroll
        for (int ks = 0; ks < 2; ks++) {
            const int kb = ks * 16;
            uint32_t ah[2][4];
            #pragma unroll
            for (int mt = 0; mt < 2; mt++) {
                int r  = wm * 32 + mt * 16 + (l >> 2);
                int kk = kb + ((l & 3) << 1);
                ah[mt][0] = *(const uint32_t*)&xh[r * XS + kk];
                ah[mt][1] = *(const uint32_t*)&xh[(r + 8) * XS + kk];
                ah[mt][2] = *(const uint32_t*)&xh[r * XS + kk + 8];
                ah[mt][3] = *(const uint32_t*)&xh[(r + 8) * XS + kk + 8];
            }
            #pragma unroll
            for (int nt = 0; nt < 4; nt++) {
                int nn2 = wn * 32 + nt * 8 + (l >> 2);
                int kg  = c0 + kb + ((l & 3) << 1);
                uint32_t bh0 = *(const uint32_t*)&Wh[nn2 * WS + kg];
                uint32_t bh1 = *(const uint32_t*)&Wh[nn2 * WS + kg + 8];
                uint32_t bl0 = *(const uint32_t*)&Wl[nn2 * WS + kg];
                uint32_t bl1 = *(const uint32_t*)&Wl[nn2 * WS + kg + 8];
                #pragma unroll
                for (int mt = 0; mt < 2; mt++) {
                    mma16816(acc[mt][nt], ah[mt][0], ah[mt][1], ah[mt][2], ah[mt][3], bh0, bh1);
                    mma16816(acc[mt][nt], ah[mt][0], ah[mt][1], ah[mt][2], ah[mt][3], bl0, bl1);
                }
            }
        }
        if (c + 1 < NC) {
            __nv_bfloat16* dh = Xh + ((c + 1) & 1) * BUF;
            #pragma unroll
            for (int ii = 0; ii < 8; ii++) {
                int i = tid + ii * 512;
                int r = i >> 5, kk = i & 31;
                dh[r * XS + kk] = __float2bfloat16(vreg[ii]);
            }
            __syncthreads();
        }
    }
}

// ---------------- 1024-thread mainloop (32 warps, warp tile 32x16) ----------------
template<int KPAD, typename F>
__device__ __forceinline__ void run_mainloop_w32(
        const __nv_bfloat16* __restrict__ Wh, const __nv_bfloat16* __restrict__ Wl,
        const int WS, __nv_bfloat16* Xh,
        float (&acc)[2][2][4], int tid, F xsrc) {
    const int l = tid & 31, wid = tid >> 5;
    const int wm = wid & 3, wn = wid >> 2;
    const int NC = KPAD / 32;
    const int BUF = 128 * XS;
    float vreg[4];

    #pragma unroll
    for (int ii = 0; ii < 4; ii++) {
        int i = tid + ii * 1024;
        vreg[ii] = xsrc(i >> 5, i & 31);
    }
    #pragma unroll
    for (int ii = 0; ii < 4; ii++) {
        int i = tid + ii * 1024;
        int r = i >> 5, kk = i & 31;
        Xh[r * XS + kk] = __float2bfloat16(vreg[ii]);
    }
    __syncthreads();

    #pragma unroll
    for (int c = 0; c < NC; c++) {
        if (c + 1 < NC) {
            #pragma unroll
            for (int ii = 0; ii < 4; ii++) {
                int i = tid + ii * 1024;
                vreg[ii] = xsrc(i >> 5, (c + 1) * 32 + (i & 31));
            }
        }
        const __nv_bfloat16* xh = Xh + (c & 1) * BUF;
        const int c0 = c * 32;
        #pragma unroll
        for (int ks = 0; ks < 2; ks++) {
            const int kb = ks * 16;
            uint32_t ah[2][4];
            #pragma unroll
            for (int mt = 0; mt < 2; mt++) {
                int r  = wm * 32 + mt * 16 + (l >> 2);
                int kk = kb + ((l & 3) << 1);
                ah[mt][0] = *(const uint32_t*)&xh[r * XS + kk];
                ah[mt][1] = *(const uint32_t*)&xh[(r + 8) * XS + kk];
                ah[mt][2] = *(const uint32_t*)&xh[r * XS + kk + 8];
                ah[mt][3] = *(const uint32_t*)&xh[(r + 8) * XS + kk + 8];
            }
            #pragma unroll
            for (int nt = 0; nt < 2; nt++) {
                int nn2 = wn * 16 + nt * 8 + (l >> 2);
                int kg  = c0 + kb + ((l & 3) << 1);
                uint32_t bh0 = *(const uint32_t*)&Wh[nn2 * WS + kg];
                uint32_t bh1 = *(const uint32_t*)&Wh[nn2 * WS + kg + 8];
                uint32_t bl0 = *(const uint32_t*)&Wl[nn2 * WS + kg];
                uint32_t bl1 = *(const uint32_t*)&Wl[nn2 * WS + kg + 8];
                #pragma unroll
                for (int mt = 0; mt < 2; mt++) {
                    mma16816(acc[mt][nt], ah[mt][0], ah[mt][1], ah[mt][2], ah[mt][3], bh0, bh1);
                    mma16816(acc[mt][nt], ah[mt][0], ah[mt][1], ah[mt][2], ah[mt][3], bl0, bl1);
                }
            }
        }
        if (c + 1 < NC) {
            __nv_bfloat16* dh = Xh + ((c + 1) & 1) * BUF;
            #pragma unroll
            for (int ii = 0; ii < 4; ii++) {
                int i = tid + ii * 1024;
                int r = i >> 5, kk = i & 31;
                dh[r * XS + kk] = __float2bfloat16(vreg[ii]);
            }
            __syncthreads();
        }
    }
}

__device__ __forceinline__ void zero_acc4(float (&acc)[2][4][4]) {
    #pragma unroll
    for (int mt = 0; mt < 2; mt++)
        #pragma unroll
        for (int nt = 0; nt < 4; nt++)
            #pragma unroll
            for (int i = 0; i < 4; i++) acc[mt][nt][i] = 0.f;
}
__device__ __forceinline__ void zero_acc2(float (&acc)[2][2][4]) {
    #pragma unroll
    for (int mt = 0; mt < 2; mt++)
        #pragma unroll
        for (int nt = 0; nt < 2; nt++)
            #pragma unroll
            for (int i = 0; i < 4; i++) acc[mt][nt][i] = 0.f;
}

// ================= dual GEMM: h0 = X@We+be (fp32); m1 = relu(X@Wf+bf) (fp16) =====
__global__ __launch_bounds__(1024) void gemm_dual(
        const float* __restrict__ X,
        const float* __restrict__ We, const float* __restrict__ be,
        const float* __restrict__ Wf, const float* __restrict__ bf,
        float* __restrict__ h0, __half* __restrict__ m1) {
    const int WSd = 72;
    extern __shared__ char sh[];
    __nv_bfloat16* Weh = (__nv_bfloat16*)sh;
    __nv_bfloat16* Wel = Weh + 128 * WSd;
    __nv_bfloat16* Wfh = Wel + 128 * WSd;
    __nv_bfloat16* Wfl = Wfh + 128 * WSd;
    __nv_bfloat16* Xh  = Wfl + 128 * WSd;   // 2 buffers
    float* bse = (float*)(Xh + 2 * 128 * XS);
    float* bsf = bse + 128;

    const int tid = threadIdx.x, l = tid & 31, wid = tid >> 5;
    const int wm = wid & 3, wn = wid >> 2, wnl = wn & 3;
    const int row0 = blockIdx.x * 128;
    const int BUF = 128 * XS;

    for (int i = tid; i < 128 * WSd; i += 1024) {
        int nn = i / WSd, k = i - nn * WSd;
        bool ok = (k < 64 && nn < HH);
        float v1 = ok ? We[k * HH + nn] : 0.f;
        float v2 = ok ? Wf[k * HH + nn] : 0.f;
        __nv_bfloat16 h, lo;
        split_bf16(v1, h, lo); Weh[i] = h; Wel[i] = lo;
        split_bf16(v2, h, lo); Wfh[i] = h; Wfl[i] = lo;
    }
    if (tid < 128) bse[tid] = (tid < HH) ? be[tid] : 0.f;
    else if (tid < 256) { int c2 = tid - 128; bsf[c2] = (c2 < HH) ? bf[c2] : 0.f; }

    const __nv_bfloat16* Whw = (wn < 4) ? Weh : Wfh;
    const __nv_bfloat16* Wlw = (wn < 4) ? Wel : Wfl;

    float acc[2][4][4];
    zero_acc4(acc);

    float vreg[4];
    #pragma unroll
    for (int ii = 0; ii < 4; ii++) {
        int i = tid + ii * 1024;
        int r = i >> 5, kk = i & 31;
        int row = row0 + r;
        vreg[ii] = (row < NN) ? X[(size_t)row * 64 + kk] : 0.f;
    }
    #pragma unroll
    for (int ii = 0; ii < 4; ii++) {
        int i = tid + ii * 1024;
        int r = i >> 5, kk = i & 31;
        Xh[r * XS + kk] = __float2bfloat16(vreg[ii]);
    }
    __syncthreads();

    #pragma unroll
    for (int c = 0; c < 2; c++) {
        if (c == 0) {
            #pragma unroll
            for (int ii = 0; ii < 4; ii++) {
                int i = tid + ii * 1024;
                int r = i >> 5, kk = i & 31;
                int row = row0 + r;
                vreg[ii] = (row < NN) ? X[(size_t)row * 64 + 32 + kk] : 0.f;
            }
        }
        const __nv_bfloat16* xh = Xh + (c & 1) * BUF;
        const int c0 = c * 32;
        #pragma unroll
        for (int ks = 0; ks < 2; ks++) {
            const int kb = ks * 16;
            #pragma unroll
            for (int mt = 0; mt < 2; mt++) {
                int r  = wm * 32 + mt * 16 + (l >> 2);
                int kk = kb + ((l & 3) << 1);
                uint32_t a0 = *(const uint32_t*)&xh[r * XS + kk];
                uint32_t a1 = *(const uint32_t*)&xh[(r + 8) * XS + kk];
                uint32_t a2 = *(const uint32_t*)&xh[r * XS + kk + 8];
                uint32_t a3 = *(const uint32_t*)&xh[(r + 8) * XS + kk + 8];
                #pragma unroll
                for (int nt = 0; nt < 4; nt++) {
                    int nn2 = wnl * 32 + nt * 8 + (l >> 2);
                    int kg  = c0 + kb + ((l & 3) << 1);
                    uint32_t bh0 = *(const uint32_t*)&Whw[nn2 * WSd + kg];
                    uint32_t bh1 = *(const uint32_t*)&Whw[nn2 * WSd + kg + 8];
                    uint32_t bl0 = *(const uint32_t*)&Wlw[nn2 * WSd + kg];
                    uint32_t bl1 = *(const uint32_t*)&Wlw[nn2 * WSd + kg + 8];
                    mma16816(acc[mt][nt], a0, a1, a2, a3, bh0, bh1);
                    mma16816(acc[mt][nt], a0, a1, a2, a3, bl0, bl1);
                }
            }
        }
        if (c == 0) {
            __nv_bfloat16* dh = Xh + BUF;
            #pragma unroll
            for (int ii = 0; ii < 4; ii++) {
                int i = tid + ii * 1024;
                int r = i >> 5, kk = i & 31;
                dh[r * XS + kk] = __float2bfloat16(vreg[ii]);
            }
            __syncthreads();
        }
    }

    #pragma unroll
    for (int mt = 0; mt < 2; mt++) {
        #pragma unroll
        for (int nt = 0; nt < 4; nt++) {
            int colL = wnl * 32 + nt * 8 + ((l & 3) << 1);
            if (colL < HH) {
                int r   = wm * 32 + mt * 16 + (l >> 2);
                int row = row0 + r;
                if (wn < 4) {
                    float v0 = acc[mt][nt][0] + bse[colL];
                    float v1 = acc[mt][nt][1] + bse[colL + 1];
                    float v2 = acc[mt][nt][2] + bse[colL];
                    float v3 = acc[mt][nt][3] + bse[colL + 1];
                    if (row < NN)     *(float2*)&h0[(size_t)row * HH + colL]       = make_float2(v0, v1);
                    if (row + 8 < NN) *(float2*)&h0[(size_t)(row + 8) * HH + colL] = make_float2(v2, v3);
                } else {
                    float v0 = fmaxf(acc[mt][nt][0] + bsf[colL], 0.f);
                    float v1 = fmaxf(acc[mt][nt][1] + bsf[colL + 1], 0.f);
                    float v2 = fmaxf(acc[mt][nt][2] + bsf[colL], 0.f);
                    float v3 = fmaxf(acc[mt][nt][3] + bsf[colL + 1], 0.f);
                    if (row < NN)     *(__half2*)&m1[(size_t)row * HH + colL]       = __floats2half2_rn(v0, v1);
                    if (row + 8 < NN) *(__half2*)&m1[(size_t)(row + 8) * HH + colL] = __floats2half2_rn(v2, v3);
                }
            }
        }
    }
}

// ================= pool2 GEMM (512 thr, 2 blocks/SM, block offset) =================
__global__ __launch_bounds__(512, 2) void gemm_pool2(
        const float* __restrict__ X, const float* __restrict__ W,
        const float* __restrict__ b, __half* __restrict__ Y, int blk0) {
    const int WS = 136;
    extern __shared__ char sh[];
    __nv_bfloat16* Wh = (__nv_bfloat16*)sh;
    __nv_bfloat16* Wl = Wh + 128 * WS;
    __nv_bfloat16* Xh = Wl + 128 * WS;
    float* bs = (float*)(Xh + 2 * 128 * XS);

    const int tid = threadIdx.x, l = tid & 31, wid = tid >> 5;
    const int wm = wid & 3, wn = wid >> 2;
    const int row0 = (blk0 + blockIdx.x) * 128;

    stage_W<108, WS, 512>(W, Wh, Wl, tid);
    if (tid < 128) bs[tid] = (tid < HH) ? b[tid] : 0.f;

    float acc[2][4][4];
    zero_acc4(acc);
    run_mainloop<128>(Wh, Wl, WS, Xh, acc, tid, SrcRow108{X, row0});

    #pragma unroll
    for (int mt = 0; mt < 2; mt++) {
        #pragma unroll
        for (int nt = 0; nt < 4; nt++) {
            int col = wn * 32 + nt * 8 + ((l & 3) << 1);
            if (col < HH) {
                int r   = wm * 32 + mt * 16 + (l >> 2);
                int row = row0 + r;
                float v0 = fmaxf(acc[mt][nt][0] + bs[col], 0.f);
                float v1 = fmaxf(acc[mt][nt][1] + bs[col + 1], 0.f);
                float v2 = fmaxf(acc[mt][nt][2] + bs[col], 0.f);
                float v3 = fmaxf(acc[mt][nt][3] + bs[col + 1], 0.f);
                if (row < NN)     *(__half2*)&Y[(size_t)row * HH + col]       = __floats2half2_rn(v0, v1);
                if (row + 8 < NN) *(__half2*)&Y[(size_t)(row + 8) * HH + col] = __floats2half2_rn(v2, v3);
            }
        }
    }
}

// ================= fused node apply (1024 threads, 32 warps, block offset) =========
template<bool POOL>
__global__ __launch_bounds__(1024) void mma_napply(
        const float* __restrict__ Hin, const __half* __restrict__ aggh,
        const float* __restrict__ W, const float* __restrict__ b,
        float* __restrict__ Hout, const int* __restrict__ gid,
        float* __restrict__ s, int blk0) {
    const int WS = 232;
    extern __shared__ char sh[];
    __nv_bfloat16* Wh = (__nv_bfloat16*)sh;
    __nv_bfloat16* Wl = Wh + 128 * WS;
    __nv_bfloat16* Xh = Wl + 128 * WS;
    float* bs  = (float*)(Xh + 2 * 128 * XS);
    int*   gds = (int*)(bs + 128);
    float* epi = (float*)sh;

    const int tid = threadIdx.x, l = tid & 31, wid = tid >> 5;
    const int wm = wid & 3, wn = wid >> 2;
    const int row0 = (blk0 + blockIdx.x) * 128;

    stage_W<216, WS, 1024>(W, Wh, Wl, tid);
    if (tid < 128) {
        bs[tid] = (tid < HH) ? b[tid] : 0.f;
        if (POOL) gds[tid] = (row0 + tid < NN) ? gid[row0 + tid] : -1;
    }

    float acc[2][2][4];
    zero_acc2(acc);
    run_mainloop_w32<224>(Wh, Wl, WS, Xh, acc, tid, SrcHinAgg{Hin, aggh, row0});

    __syncthreads();
    #pragma unroll
    for (int mt = 0; mt < 2; mt++) {
        #pragma unroll
        for (int nt = 0; nt < 2; nt++) {
            int col = wn * 16 + nt * 8 + ((l & 3) << 1);
            int r   = wm * 32 + mt * 16 + (l >> 2);
            *(float2*)&epi[r * ES + col] =
                make_float2(acc[mt][nt][0] + bs[col], acc[mt][nt][1] + bs[col + 1]);
            *(float2*)&epi[(r + 8) * ES + col] =
                make_float2(acc[mt][nt][2] + bs[col], acc[mt][nt][3] + bs[col + 1]);
        }
    }
    __syncthreads();

    #pragma unroll
    for (int rr = 0; rr < 4; rr++) {
        int r = wid * 4 + rr;
        int row = row0 + r;
        if (row >= NN) continue;
        float v[4]; float sn = 0.f;
        #pragma unroll
        for (int j = 0; j < 4; j++) {
            int c = l + 32 * j;
            v[j] = (c < HH) ? epi[r * ES + c] : 0.f;
            sn += v[j] * v[j];
        }
        #pragma unroll
        for (int off2 = 16; off2 > 0; off2 >>= 1)
            sn += __shfl_xor_sync(0xffffffffu, sn, off2);
        float inv = 1.f / fmaxf(sqrtf(sn), 1e-12f);
        #pragma unroll
        for (int j = 0; j < 4; j++) {
            int c = l + 32 * j;
            if (c < HH) {
                float o = Hin[(size_t)row * HH + c] + fmaxf(v[j] * inv, 0.f);
                if (POOL) epi[r * ES + c] = o;
                else      Hout[(size_t)row * HH + c] = o;
            }
        }
    }

    if (POOL) {
        __syncthreads();
        int col = tid & 127, seg = tid >> 7;
        if (col < HH) {
            float a = 0.f; int curg = -1;
            #pragma unroll 4
            for (int r = seg * 16; r < seg * 16 + 16; r++) {
                int g = gds[r];
                if (g < 0) break;
                if (g != curg) {
                    if (curg >= 0) atomicAdd(&s[curg * HH + col], a);
                    curg = g; a = 0.f;
                }
                a += epi[r * ES + col];
            }
            if (curg >= 0) atomicAdd(&s[curg * HH + col], a);
        }
    }
}

// ================= weight fusion =================
__global__ __launch_bounds__(256) void fuse_w(
        const float* __restrict__ We, const float* __restrict__ be,
        const float* __restrict__ Wp, const float* __restrict__ bp,
        float* __restrict__ Wf, float* __restrict__ bf) {
    __shared__ float sWp[HH * HH];
    for (int i = threadIdx.x; i < HH * HH; i += 256) sWp[i] = Wp[i];
    __syncthreads();
    int t = blockIdx.x * 256 + threadIdx.x;
    if (t < 64 * HH) {
        int i = t / HH, j = t - (t / HH) * HH;
        const float* we = We + i * HH;
        float s0 = 0.f, s1 = 0.f;
        #pragma unroll 4
        for (int k = 0; k < HH; k += 2) {
            s0 = fmaf(we[k],     sWp[k * HH + j],       s0);
            s1 = fmaf(we[k + 1], sWp[(k + 1) * HH + j], s1);
        }
        Wf[t] = s0 + s1;
    } else if (t < 64 * HH + HH) {
        int j = t - 64 * HH;
        float s0 = bp[j], s1 = 0.f;
        #pragma unroll 4
        for (int k = 0; k < HH; k += 2) {
            s0 = fmaf(be[k],     sWp[k * HH + j],       s0);
            s1 = fmaf(be[k + 1], sWp[(k + 1) * HH + j], s1);
        }
        bf[j] = s0 + s1;
    }
}

// ================= graph prep =================
__global__ void deg_cnt_kernel(const int* __restrict__ dst, const int* __restrict__ gid,
                               int* __restrict__ degi, float* __restrict__ cnt) {
    int tk = blockIdx.x * blockDim.x + threadIdx.x;
    if (tk < EE) atomicAdd(&degi[dst[tk]], 1);
    if (tk < NN) atomicAdd(&cnt[gid[tk]], 1.f);
}

__global__ void scan_block(const int* __restrict__ degi, int* __restrict__ off,
                           int* __restrict__ cur) {
    __shared__ int wt[32];
    const int PER = 49;
    int t = threadIdx.x, lane = t & 31, w = t >> 5;
    int base = t * PER;
    int sum = 0;
    for (int j = 0; j < PER; j++) {
        int idx = base + j;
        if (idx < NN) sum += degi[idx];
    }
    int v = sum;
    #pragma unroll
    for (int d = 1; d < 32; d <<= 1) {
        int u = __shfl_up_sync(0xffffffffu, v, d);
        if (lane >= d) v += u;
    }
    if (lane == 31) wt[w] = v;
    __syncthreads();
    if (w == 0) {
        int x = wt[lane];
        #pragma unroll
        for (int d = 1; d < 32; d <<= 1) {
            int u = __shfl_up_sync(0xffffffffu, x, d);
            if (lane >= d) x += u;
        }
        wt[lane] = x;
    }
    __syncthreads();
    int run = v - sum + (w > 0 ? wt[w - 1] : 0);
    for (int j = 0; j < PER; j++) {
        int idx = base + j;
        if (idx < NN) {
            int d0 = degi[idx];
            off[idx] = run;
            cur[idx] = run;
            run += d0;
        }
    }
}

__global__ void csr_fill(const int* __restrict__ src, const int* __restrict__ dst,
                         int* __restrict__ cur, int* __restrict__ csr) {
    int e = blockIdx.x * blockDim.x + threadIdx.x;
    if (e < EE) {
        int d = dst[e];
        int pidx = atomicAdd(&cur[d], 1);
        csr[pidx] = src[e];
    }
}

// ===== gather over node range [n0, n1): one warp per node; c -> fp16; unroll 8 =====
__global__ void gather_agg(const __half* __restrict__ m, const int* __restrict__ off,
                           const int* __restrict__ csr, __half* __restrict__ aggh,
                           int n0, int n1) {
    int w = n0 + ((blockIdx.x * blockDim.x + threadIdx.x) >> 5);
    int lane = threadIdx.x & 31;
    if (w >= n1 || lane >= CH4) return;
    int s0 = off[w];
    int s1 = (w + 1 < NN) ? off[w + 1] : EE;
    float4 a0 = make_float4(0.f,0.f,0.f,0.f), a1 = a0, a2 = a0, a3 = a0;
    int j = s0;
    for (; j + 7 < s1; j += 8) {
        int idx[8];
        #pragma unroll
        for (int u = 0; u < 8; u++) idx[u] = csr[j + u];
        uint2 q[8];
        #pragma unroll
        for (int u = 0; u < 8; u++)
            q[u] = *(const uint2*)(m + (size_t)idx[u] * HH + lane * 4);
        #pragma unroll
        for (int u = 0; u < 8; u++) {
            float2 f0 = __half22float2(*(__half2*)&q[u].x);
            float2 f1 = __half22float2(*(__half2*)&q[u].y);
            float4& a = (u & 3) == 0 ? a0 : (u & 3) == 1 ? a1 : (u & 3) == 2 ? a2 : a3;
            a.x += f0.x; a.y += f0.y; a.z += f1.x; a.w += f1.y;
        }
    }
    for (; j < s1; j++) {
        int i0 = csr[j];
        uint2 q0 = *(const uint2*)(m + (size_t)i0 * HH + lane * 4);
        float2 f0 = __half22float2(*(__half2*)&q0.x);
        float2 f1 = __half22float2(*(__half2*)&q0.y);
        a0.x += f0.x; a0.y += f0.y; a0.z += f1.x; a0.w += f1.y;
    }
    float inv = 1.f / fmaxf((float)(s1 - s0), 1.f);
    a0.x = (a0.x + a1.x + a2.x + a3.x) * inv;
    a0.y = (a0.y + a1.y + a2.y + a3.y) * inv;
    a0.z = (a0.z + a1.z + a2.z + a3.z) * inv;
    a0.w = (a0.w + a1.w + a2.w + a3.w) * inv;
    __half2 o0 = __floats2half2_rn(a0.x, a0.y);
    __half2 o1 = __floats2half2_rn(a0.z, a0.w);
    *(__half2*)&aggh[(size_t)w * HH + lane * 4]     = o0;
    *(__half2*)&aggh[(size_t)w * HH + lane * 4 + 2] = o1;
}

// ================= readout finalize =================
__global__ void finalize(const float* __restrict__ s, const float* __restrict__ cnt,
                         float* __restrict__ out) {
    int tk = blockIdx.x * blockDim.x + threadIdx.x;
    if (tk < GG * HH) {
        int g = tk / HH;
        out[tk] = s[tk] / fmaxf(cnt[g], 1.f);
    }
}

// ================= launch =================
extern "C" void kernel_launch(void* const* d_in, const int* in_sizes, int n_in,
                              void* d_out, int out_size) {
    const float* nodes_feat = (const float*)d_in[0];
    const int*   src  = (const int*)d_in[4];
    const int*   dst  = (const int*)d_in[5];
    const int*   gid  = (const int*)d_in[6];
    const float* W_emb = (const float*)d_in[7];
    const float* b_emb = (const float*)d_in[8];
    const float* Wp1   = (const float*)d_in[9];
    const float* bp1   = (const float*)d_in[10];
    const float* Wn1   = (const float*)d_in[11];
    const float* bn1   = (const float*)d_in[12];
    const float* Wp2   = (const float*)d_in[13];
    const float* bp2   = (const float*)d_in[14];
    const float* Wn2   = (const float*)d_in[15];
    const float* bn2   = (const float*)d_in[16];
    float* out = (float*)d_out;

    float *p_h0, *p_h1, *p_s, *p_cnt, *p_wf, *p_bf;
    __half *p_m, *p_aggh;
    int *p_degi, *p_off, *p_cur, *p_csr;
    cudaGetSymbolAddress((void**)&p_h0,   g_h0);
    cudaGetSymbolAddress((void**)&p_h1,   g_h1);
    cudaGetSymbolAddress((void**)&p_m,    g_m);
    cudaGetSymbolAddress((void**)&p_aggh, g_aggh);
    cudaGetSymbolAddress((void**)&p_s,    g_s);
    cudaGetSymbolAddress((void**)&p_cnt,  g_cnt);
    cudaGetSymbolAddress((void**)&p_wf,   g_wf);
    cudaGetSymbolAddress((void**)&p_bf,   g_bf);
    cudaGetSymbolAddress((void**)&p_degi, g_degi);
    cudaGetSymbolAddress((void**)&p_off,  g_off);
    cudaGetSymbolAddress((void**)&p_cur,  g_cur);
    cudaGetSymbolAddress((void**)&p_csr,  g_csr);

    const int smem_dual = 4*(128*72*2) + (2*128*XS*2) + 1024;   //  95,232
    const int smem_pool = 2*(128*136*2) + (2*128*XS*2) + 512;   //  90,624
    const int smem_na   = 2*(128*232*2) + (2*128*XS*2) + 1024;  // 140,288
    cudaFuncSetAttribute(gemm_dual,         cudaFuncAttributeMaxDynamicSharedMemorySize, smem_dual);
    cudaFuncSetAttribute(gemm_pool2,        cudaFuncAttributeMaxDynamicSharedMemorySize, smem_pool);
    cudaFuncSetAttribute(mma_napply<false>, cudaFuncAttributeMaxDynamicSharedMemorySize, smem_na);
    cudaFuncSetAttribute(mma_napply<true>,  cudaFuncAttributeMaxDynamicSharedMemorySize, smem_na);

    const int NBB = NB - NBA;   // 195

    // fork: fuse_w (s3) and CSR chain (s2) start immediately
    cudaEventRecord(g_aux.fork, 0);
    cudaStreamWaitEvent(g_aux.s3, g_aux.fork, 0);
    cudaStreamWaitEvent(g_aux.s2, g_aux.fork, 0);

    // s3: weight folding
    fuse_w<<<28, 256, 0, g_aux.s3>>>(W_emb, b_emb, Wp1, bp1, p_wf, p_bf);
    cudaEventRecord(g_aux.fw, g_aux.s3);

    // s2: CSR chain
    cudaMemsetAsync(p_degi, 0, (size_t)NN * sizeof(int), g_aux.s2);
    cudaMemsetAsync(p_cnt,  0, (size_t)GG * sizeof(float), g_aux.s2);
    deg_cnt_kernel<<<(EE + 255) / 256, 256, 0, g_aux.s2>>>(dst, gid, p_degi, p_cnt);
    scan_block<<<1, 1024, 0, g_aux.s2>>>(p_degi, p_off, p_cur);
    csr_fill<<<(EE + 255) / 256, 256, 0, g_aux.s2>>>(src, dst, p_cur, p_csr);
    cudaEventRecord(g_aux.csrdone, g_aux.s2);

    // default: readout zero-init, then dual
    cudaMemsetAsync(p_s, 0, (size_t)GG * HH * sizeof(float));
    cudaStreamWaitEvent(0, g_aux.fw, 0);
    gemm_dual<<<NB, 1024, smem_dual>>>(nodes_feat, W_emb, b_emb, p_wf, p_bf, p_h0, p_m);
    cudaEventRecord(g_aux.duald, 0);

    // ---- layer 1, half B on s2 ----
    cudaStreamWaitEvent(g_aux.s2, g_aux.duald, 0);
    gather_agg<<<((NN - NSPLIT) * 32 + 255) / 256, 256, 0, g_aux.s2>>>(p_m, p_off, p_csr, p_aggh, NSPLIT, NN);
    mma_napply<false><<<NBB, 1024, smem_na, g_aux.s2>>>(p_h0, p_aggh, Wn1, bn1, p_h1, nullptr, nullptr, NBA);
    gemm_pool2<<<NBB, 512, smem_pool, g_aux.s2>>>(p_h1, Wp2, bp2, p_m, NBA);
    cudaEventRecord(g_aux.evB, g_aux.s2);

    // ---- layer 1, half A on default ----
    cudaStreamWaitEvent(0, g_aux.csrdone, 0);
    gather_agg<<<(NSPLIT * 32 + 255) / 256, 256>>>(p_m, p_off, p_csr, p_aggh, 0, NSPLIT);
    mma_napply<false><<<NBA, 1024, smem_na>>>(p_h0, p_aggh, Wn1, bn1, p_h1, nullptr, nullptr, 0);
    gemm_pool2<<<NBA, 512, smem_pool>>>(p_h1, Wp2, bp2, p_m, 0);
    cudaEventRecord(g_aux.poolA, 0);

    // ---- layer 2, half B on s2 ----
    cudaStreamWaitEvent(g_aux.s2, g_aux.poolA, 0);
    gather_agg<<<((NN - NSPLIT) * 32 + 255) / 256, 256, 0, g_aux.s2>>>(p_m, p_off, p_csr, p_aggh, NSPLIT, NN);
    mma_napply<true><<<NBB, 1024, smem_na, g_aux.s2>>>(p_h1, p_aggh, Wn2, bn2, nullptr, gid, p_s, NBA);
    cudaEventRecord(g_aux.evB2, g_aux.s2);

    // ---- layer 2, half A on default ----
    cudaStreamWaitEvent(0, g_aux.evB, 0);
    gather_agg<<<(NSPLIT * 32 + 255) / 256, 256>>>(p_m, p_off, p_csr, p_aggh, 0, NSPLIT);
    mma_napply<true><<<NBA, 1024, smem_na>>>(p_h1, p_aggh, Wn2, bn2, nullptr, gid, p_s, 0);

    // join + finalize
    cudaStreamWaitEvent(0, g_aux.evB2, 0);
    finalize<<<(GG * HH + 127) / 128, 128>>>(p_s, p_cnt, out);
}